// round 12
// baseline (speedup 1.0000x reference)
#include <cuda_runtime.h>
#include <cuda_bf16.h>
#include <mma.h>
#include <math.h>
#include <cstdint>

using namespace nvcuda;

// ---------------- problem constants ----------------
#define BB 4
#define NN 2048
#define MV 576
#define CC 512
#define HH 8
#define KVH 2
#define DD 64
#define EE 8
#define TOPK 2
#define FF 2048
#define TOK (BB*NN)
#define KVDIM (KVH*DD)       // 128
#define EROWS 8192

// weight buffer offsets (elements)
#define SZ_QO (CC*CC)
#define SZ_KV (CC*KVDIM)
#define OFF_SAWQ 0
#define OFF_SAWK (OFF_SAWQ+SZ_QO)
#define OFF_SAWV (OFF_SAWK+SZ_KV)
#define OFF_SAWO (OFF_SAWV+SZ_KV)
#define OFF_CAWQ (OFF_SAWO+SZ_QO)
#define OFF_CAWK (OFF_CAWQ+SZ_QO)
#define OFF_CAWV (OFF_CAWK+SZ_KV)
#define OFF_CAWO (OFF_CAWV+SZ_KV)
#define OFF_EW1  (OFF_CAWO+SZ_QO)
#define OFF_EW2  (OFF_EW1 + (size_t)EE*CC*FF)
#define WTOT     (OFF_EW2 + (size_t)EE*FF*CC)

// ---------------- static scratch ----------------
__device__ float g_h  [(size_t)TOK*CC];     // fp32 LN out (router)
__device__ float g_x1 [(size_t)TOK*CC];
__device__ float g_x2 [(size_t)TOK*CC];
__device__ float g_eo [(size_t)EE*EROWS*CC];
__device__ __nv_bfloat16 g_h_hi [(size_t)TOK*CC];
__device__ __nv_bfloat16 g_h_lo [(size_t)TOK*CC];
__device__ __nv_bfloat16 g_q_hi [(size_t)TOK*CC];
__device__ __nv_bfloat16 g_q_lo [(size_t)TOK*CC];
__device__ __nv_bfloat16 g_k_hi [(size_t)TOK*KVDIM];
__device__ __nv_bfloat16 g_k_lo [(size_t)TOK*KVDIM];
__device__ __nv_bfloat16 g_v_hi [(size_t)TOK*KVDIM];
__device__ __nv_bfloat16 g_v_lo [(size_t)TOK*KVDIM];
__device__ __nv_bfloat16 g_att_hi[(size_t)TOK*CC];
__device__ __nv_bfloat16 g_att_lo[(size_t)TOK*CC];
__device__ __nv_bfloat16 g_vis_hi[(size_t)BB*MV*CC];
__device__ __nv_bfloat16 g_vis_lo[(size_t)BB*MV*CC];
__device__ __nv_bfloat16 g_mid_hi[(size_t)EE*EROWS*FF];
__device__ __nv_bfloat16 g_mid_lo[(size_t)EE*EROWS*FF];
__device__ __nv_bfloat16 g_w_hi[WTOT];
__device__ __nv_bfloat16 g_w_lo[WTOT];
__device__ int   g_count[EE];
__device__ float g_Psum[EE];
__device__ int   g_tokrow [TOK*TOPK];
__device__ float g_tokgate[TOK*TOPK];
__device__ int   g_tok_of_row[EE*EROWS];

// ---------------- helpers ----------------
__device__ __forceinline__ void split1(float v, __nv_bfloat16& h, __nv_bfloat16& l) {
    h = __float2bfloat16(v);
    l = __float2bfloat16(v - __bfloat162float(h));
}
__device__ __forceinline__ unsigned pk2(float lo, float hi) {
    unsigned r;
    asm("cvt.rn.bf16x2.f32 %0, %1, %2;" : "=r"(r) : "f"(hi), "f"(lo));
    return r;
}
__device__ __forceinline__ float bfrt(float x) {
    return __bfloat162float(__float2bfloat16(x));
}
__device__ __forceinline__ void mma16816(float* c, const unsigned* a, const unsigned* b) {
    asm volatile(
        "mma.sync.aligned.m16n8k16.row.col.f32.bf16.bf16.f32 "
        "{%0,%1,%2,%3},{%4,%5,%6,%7},{%8,%9},{%0,%1,%2,%3};"
        : "+f"(c[0]), "+f"(c[1]), "+f"(c[2]), "+f"(c[3])
        : "r"(a[0]), "r"(a[1]), "r"(a[2]), "r"(a[3]), "r"(b[0]), "r"(b[1]));
}
// 16B async copy; zero-fill when !valid
__device__ __forceinline__ void cp16(void* dst, const void* src, bool valid) {
    unsigned d = (unsigned)__cvta_generic_to_shared(dst);
    int sz = valid ? 16 : 0;
    asm volatile("cp.async.cg.shared.global [%0], [%1], 16, %2;\n" :: "r"(d), "l"(src), "r"(sz));
}
#define CP_COMMIT asm volatile("cp.async.commit_group;\n" ::: "memory")
#define CP_WAIT0  asm volatile("cp.async.wait_group 0;\n" ::: "memory")
#define CP_WAIT1  asm volatile("cp.async.wait_group 1;\n" ::: "memory")

// ---------------- fp32 -> hi/lo bf16 conversion ----------------
__global__ void conv_kernel(const float* __restrict__ src, __nv_bfloat16* __restrict__ hi,
                            __nv_bfloat16* __restrict__ lo, int n) {
    int i = (blockIdx.x * blockDim.x + threadIdx.x) * 4;
    if (i >= n) return;
    float4 v = *(const float4*)(src + i);
    __align__(8) __nv_bfloat16 h[4], l[4];
    split1(v.x, h[0], l[0]); split1(v.y, h[1], l[1]);
    split1(v.z, h[2], l[2]); split1(v.w, h[3], l[3]);
    *(uint2*)(hi + i) = *(uint2*)h;
    *(uint2*)(lo + i) = *(uint2*)l;
}

// ---------------- LayerNorm (fp32 + hi/lo bf16 out) ----------------
__global__ void ln_kernel(const float* __restrict__ x, const float* __restrict__ g,
                          const float* __restrict__ b, float* __restrict__ o,
                          __nv_bfloat16* __restrict__ ohi, __nv_bfloat16* __restrict__ olo) {
    int t = blockIdx.x;
    int tid = threadIdx.x;
    const float* xr = x + (size_t)t * CC;
    float v0 = xr[tid], v1 = xr[tid + 256];
    __shared__ float red[256];
    red[tid] = v0 + v1; __syncthreads();
    for (int off = 128; off > 0; off >>= 1) {
        if (tid < off) red[tid] += red[tid + off];
        __syncthreads();
    }
    float mu = red[0] * (1.0f / CC);
    __syncthreads();
    float d0 = v0 - mu, d1 = v1 - mu;
    red[tid] = d0 * d0 + d1 * d1; __syncthreads();
    for (int off = 128; off > 0; off >>= 1) {
        if (tid < off) red[tid] += red[tid + off];
        __syncthreads();
    }
    float rstd = rsqrtf(red[0] * (1.0f / CC) + 1e-6f);
    size_t base = (size_t)t * CC;
    float r0 = d0 * rstd * g[tid]       + b[tid];
    float r1 = d1 * rstd * g[tid + 256] + b[tid + 256];
    o[base + tid] = r0; o[base + tid + 256] = r1;
    __nv_bfloat16 h, l;
    split1(r0, h, l); ohi[base + tid] = h;       olo[base + tid] = l;
    split1(r1, h, l); ohi[base + tid + 256] = h; olo[base + tid + 256] = l;
}

// ---------------- wmma split-bf16 GEMM core, 2-stage cp.async pipeline ----------------
#define APAD 40
#define BPAD 136
#define CPAD 132
struct SmemGemm {
    __nv_bfloat16 Ah[2][128][APAD];
    __nv_bfloat16 Al[2][128][APAD];
    __nv_bfloat16 Bh[2][32][BPAD];
    __nv_bfloat16 Bl[2][32][BPAD];
};
#define GEMM_SMEM_BYTES 75776   // sizeof(SmemGemm)=75776 > Cs staging 128*132*4=67584

typedef wmma::fragment<wmma::accumulator, 16, 16, 16, float> AccFrag;

__device__ __forceinline__ void wmma_core(
        const __nv_bfloat16* __restrict__ Ahg, const __nv_bfloat16* __restrict__ Alg,
        const __nv_bfloat16* __restrict__ Bhg, const __nv_bfloat16* __restrict__ Blg,
        const int* __restrict__ tokidx,
        int Mr, int Nc, int Kd, int row0, int col0,
        SmemGemm* S, AccFrag (&acc)[2][4]) {
    int tid = threadIdx.x;
    int w = tid >> 5, wm = w & 3, wn = w >> 2;
    int ra = tid >> 1, kc = (tid & 1) * 16;     // A: 128 rows x 32 cols
    int rb = tid >> 3, cb = (tid & 7) * 16;     // B: 32 rows x 128 cols

    size_t arow; bool avalid;
    if (tokidx) {
        int tok = tokidx[ra];
        avalid = (tok >= 0);
        arow = (size_t)(avalid ? tok : 0) * Kd;
    } else {
        int gr = row0 + ra;
        avalid = (gr < Mr);
        arow = (size_t)(avalid ? gr : 0) * Kd;
    }

    int nch = Kd / 32;
    auto issue = [&](int c) {
        int k0 = c * 32, buf = c & 1;
        size_t ab = arow + k0 + kc;
        cp16(&S->Ah[buf][ra][kc],     Ahg + ab,     avalid);
        cp16(&S->Ah[buf][ra][kc + 8], Ahg + ab + 8, avalid);
        cp16(&S->Al[buf][ra][kc],     Alg + ab,     avalid);
        cp16(&S->Al[buf][ra][kc + 8], Alg + ab + 8, avalid);
        size_t bb = (size_t)(k0 + rb) * Nc + col0 + cb;
        cp16(&S->Bh[buf][rb][cb],     Bhg + bb,     true);
        cp16(&S->Bh[buf][rb][cb + 8], Bhg + bb + 8, true);
        cp16(&S->Bl[buf][rb][cb],     Blg + bb,     true);
        cp16(&S->Bl[buf][rb][cb + 8], Blg + bb + 8, true);
        CP_COMMIT;
    };

    issue(0);
    #pragma unroll 1
    for (int c = 0; c < nch; c++) {
        if (c + 1 < nch) { issue(c + 1); CP_WAIT1; } else { CP_WAIT0; }
        __syncthreads();
        int buf = c & 1;
        #pragma unroll
        for (int ks = 0; ks < 2; ks++) {
            wmma::fragment<wmma::matrix_a, 16,16,16, __nv_bfloat16, wmma::row_major> ah[2], al[2];
            wmma::fragment<wmma::matrix_b, 16,16,16, __nv_bfloat16, wmma::row_major> bh[4], bl[4];
            #pragma unroll
            for (int i = 0; i < 2; i++) {
                wmma::load_matrix_sync(ah[i], &S->Ah[buf][wm*32 + i*16][ks*16], APAD);
                wmma::load_matrix_sync(al[i], &S->Al[buf][wm*32 + i*16][ks*16], APAD);
            }
            #pragma unroll
            for (int j = 0; j < 4; j++) {
                wmma::load_matrix_sync(bh[j], &S->Bh[buf][ks*16][wn*64 + j*16], BPAD);
                wmma::load_matrix_sync(bl[j], &S->Bl[buf][ks*16][wn*64 + j*16], BPAD);
            }
            #pragma unroll
            for (int i = 0; i < 2; i++)
                #pragma unroll
                for (int j = 0; j < 4; j++) {
                    wmma::mma_sync(acc[i][j], ah[i], bh[j], acc[i][j]);
                    wmma::mma_sync(acc[i][j], ah[i], bl[j], acc[i][j]);
                    wmma::mma_sync(acc[i][j], al[i], bh[j], acc[i][j]);
                }
        }
        __syncthreads();   // readers done before buf is overwritten two chunks later
    }
}

__device__ __forceinline__ void stage_acc(AccFrag (&acc)[2][4], float (*Cs)[CPAD], int tid) {
    int w = tid >> 5, wm = w & 3, wn = w >> 2;
    #pragma unroll
    for (int i = 0; i < 2; i++)
        #pragma unroll
        for (int j = 0; j < 4; j++)
            wmma::store_matrix_sync(&Cs[wm*32 + i*16][wn*64 + j*16], acc[i][j],
                                    CPAD, wmma::mem_row_major);
    __syncthreads();
}

// ---------------- generic GEMM: fp32 out (bias/resid) OR hi/lo bf16 out ----------------
__global__ void __launch_bounds__(256) gemm128(
        const __nv_bfloat16* __restrict__ Ahg, const __nv_bfloat16* __restrict__ Alg,
        int woff, const float* __restrict__ bias, const float* __restrict__ resid,
        float* __restrict__ out,
        __nv_bfloat16* __restrict__ ohi, __nv_bfloat16* __restrict__ olo,
        int Mr, int Nc, int Kd) {
    extern __shared__ char smraw[];
    SmemGemm* S = (SmemGemm*)smraw;
    float (*Cs)[CPAD] = (float(*)[CPAD])smraw;
    int tid = threadIdx.x;
    int row0 = blockIdx.y * 128, col0 = blockIdx.x * 128;
    AccFrag acc[2][4];
    #pragma unroll
    for (int i = 0; i < 2; i++)
        #pragma unroll
        for (int j = 0; j < 4; j++) wmma::fill_fragment(acc[i][j], 0.0f);
    wmma_core(Ahg, Alg, g_w_hi + woff, g_w_lo + woff, nullptr, Mr, Nc, Kd, row0, col0, S, acc);
    stage_acc(acc, Cs, tid);
    #pragma unroll
    for (int u = 0; u < 16; u++) {
        int f = tid + u * 256;
        int r = f >> 5, c = (f & 31) * 4;
        int gr = row0 + r;
        if (gr >= Mr) continue;
        int gc = col0 + c;
        float4 v = *(float4*)&Cs[r][c];
        if (bias) { v.x += bias[gc]; v.y += bias[gc+1]; v.z += bias[gc+2]; v.w += bias[gc+3]; }
        if (resid) {
            float4 rr = *(const float4*)(resid + (size_t)gr * Nc + gc);
            v.x += rr.x; v.y += rr.y; v.z += rr.z; v.w += rr.w;
        }
        if (out) {
            *(float4*)(out + (size_t)gr * Nc + gc) = v;
        } else {
            __align__(8) __nv_bfloat16 hh[4], ll[4];
            split1(v.x, hh[0], ll[0]); split1(v.y, hh[1], ll[1]);
            split1(v.z, hh[2], ll[2]); split1(v.w, hh[3], ll[3]);
            *(uint2*)(ohi + (size_t)gr * Nc + gc) = *(uint2*)hh;
            *(uint2*)(olo + (size_t)gr * Nc + gc) = *(uint2*)ll;
        }
    }
}

// ---------------- fused K+V projection -> hi/lo bf16 ----------------
__global__ void __launch_bounds__(256) kvgemm128(
        const __nv_bfloat16* __restrict__ Ahg, const __nv_bfloat16* __restrict__ Alg,
        int woffk, const float* __restrict__ bk,
        int woffv, const float* __restrict__ bv,
        __nv_bfloat16* __restrict__ okh, __nv_bfloat16* __restrict__ okl,
        __nv_bfloat16* __restrict__ ovh, __nv_bfloat16* __restrict__ ovl,
        int Mr, int Kd) {
    extern __shared__ char smraw[];
    SmemGemm* S = (SmemGemm*)smraw;
    float (*Cs)[CPAD] = (float(*)[CPAD])smraw;
    int woff          = (blockIdx.x == 0) ? woffk : woffv;
    const float* bias = (blockIdx.x == 0) ? bk : bv;
    __nv_bfloat16* oh = (blockIdx.x == 0) ? okh : ovh;
    __nv_bfloat16* ol = (blockIdx.x == 0) ? okl : ovl;
    int tid = threadIdx.x;
    int row0 = blockIdx.y * 128;
    AccFrag acc[2][4];
    #pragma unroll
    for (int i = 0; i < 2; i++)
        #pragma unroll
        for (int j = 0; j < 4; j++) wmma::fill_fragment(acc[i][j], 0.0f);
    wmma_core(Ahg, Alg, g_w_hi + woff, g_w_lo + woff, nullptr, Mr, KVDIM, Kd, row0, 0, S, acc);
    stage_acc(acc, Cs, tid);
    #pragma unroll
    for (int u = 0; u < 16; u++) {
        int f = tid + u * 256;
        int r = f >> 5, c = (f & 31) * 4;
        int gr = row0 + r;
        if (gr >= Mr) continue;
        float4 v = *(float4*)&Cs[r][c];
        v.x += bias[c]; v.y += bias[c+1]; v.z += bias[c+2]; v.w += bias[c+3];
        __align__(8) __nv_bfloat16 hh[4], ll[4];
        split1(v.x, hh[0], ll[0]); split1(v.y, hh[1], ll[1]);
        split1(v.z, hh[2], ll[2]); split1(v.w, hh[3], ll[3]);
        *(uint2*)(oh + (size_t)gr * KVDIM + c) = *(uint2*)hh;
        *(uint2*)(ol + (size_t)gr * KVDIM + c) = *(uint2*)ll;
    }
}

// ---------------- FA2 flash attention: mma.m16n8k16 split-bf16 ----------------
// Heavy-first scheduling: qt is reversed so the deepest causal tiles launch first,
// letting light tiles pack the final wave (reduces wave-2 tail).
#define KPAD 72
__global__ void __launch_bounds__(256) flash_mma(
        const __nv_bfloat16* __restrict__ qhi, const __nv_bfloat16* __restrict__ qlo,
        const __nv_bfloat16* __restrict__ khi, const __nv_bfloat16* __restrict__ klo,
        const __nv_bfloat16* __restrict__ vhi, const __nv_bfloat16* __restrict__ vlo,
        __nv_bfloat16* __restrict__ ohi, __nv_bfloat16* __restrict__ olo,
        int n_kv, int causal) {
    __shared__ __nv_bfloat16 Kh[64][KPAD], Kl[64][KPAD], Vth[64][KPAD], Vtl[64][KPAD];
    int qt = gridDim.x - 1 - blockIdx.x;   // heavy (large-qt) blocks scheduled first
    int h = blockIdx.y, b = blockIdx.z;
    int g = h >> 2;
    int tid = threadIdx.x, w = tid >> 5, lane = tid & 31;
    int r0 = lane >> 2, tq = lane & 3;
    int qrow = qt * 128 + w * 16 + r0;

    unsigned qah[4][4], qal[4][4];
    {
        const __nv_bfloat16* q0h = qhi + ((size_t)(b * NN + qrow)) * CC + h * DD;
        const __nv_bfloat16* q1h = qhi + ((size_t)(b * NN + qrow + 8)) * CC + h * DD;
        const __nv_bfloat16* q0l = qlo + ((size_t)(b * NN + qrow)) * CC + h * DD;
        const __nv_bfloat16* q1l = qlo + ((size_t)(b * NN + qrow + 8)) * CC + h * DD;
        #pragma unroll
        for (int ks = 0; ks < 4; ks++) {
            int c = ks * 16 + tq * 2;
            qah[ks][0] = *(const unsigned*)(q0h + c);
            qah[ks][1] = *(const unsigned*)(q1h + c);
            qah[ks][2] = *(const unsigned*)(q0h + c + 8);
            qah[ks][3] = *(const unsigned*)(q1h + c + 8);
            qal[ks][0] = *(const unsigned*)(q0l + c);
            qal[ks][1] = *(const unsigned*)(q1l + c);
            qal[ks][2] = *(const unsigned*)(q0l + c + 8);
            qal[ks][3] = *(const unsigned*)(q1l + c + 8);
        }
    }

    float m0 = -1e30f, m1 = -1e30f, l0 = 0.0f, l1 = 0.0f;
    float o[8][4] = {};

    int key_l = tid >> 2, dseg = (tid & 3) * 16;
    int nkt = causal ? (2 * qt + 2) : (n_kv / 64);
    for (int kt = 0; kt < nkt; kt++) {
        __syncthreads();
        {
            size_t base = ((size_t)(b * n_kv + kt * 64 + key_l)) * KVDIM + g * DD + dseg;
            *(uint4*)&Kh[key_l][dseg]     = *(const uint4*)(khi + base);
            *(uint4*)&Kh[key_l][dseg + 8] = *(const uint4*)(khi + base + 8);
            *(uint4*)&Kl[key_l][dseg]     = *(const uint4*)(klo + base);
            *(uint4*)&Kl[key_l][dseg + 8] = *(const uint4*)(klo + base + 8);
            const __nv_bfloat16* vh = vhi + base;
            const __nv_bfloat16* vl = vlo + base;
            #pragma unroll
            for (int i = 0; i < 16; i++) {
                Vth[dseg + i][key_l] = vh[i];
                Vtl[dseg + i][key_l] = vl[i];
            }
        }
        __syncthreads();

        float sc[8][4] = {};
        #pragma unroll
        for (int nt = 0; nt < 8; nt++) {
            int krow = nt * 8 + r0;
            #pragma unroll
            for (int ks = 0; ks < 4; ks++) {
                int c = ks * 16 + tq * 2;
                unsigned bh[2], bl[2];
                bh[0] = *(const unsigned*)&Kh[krow][c];
                bh[1] = *(const unsigned*)&Kh[krow][c + 8];
                bl[0] = *(const unsigned*)&Kl[krow][c];
                bl[1] = *(const unsigned*)&Kl[krow][c + 8];
                mma16816(sc[nt], qah[ks], bh);
                mma16816(sc[nt], qah[ks], bl);
                mma16816(sc[nt], qal[ks], bh);
            }
        }
        bool maskit = causal && (kt >= 2 * qt);
        #pragma unroll
        for (int nt = 0; nt < 8; nt++) {
            #pragma unroll
            for (int j = 0; j < 4; j++) {
                float v = sc[nt][j] * 0.125f;
                if (maskit) {
                    int col = kt * 64 + nt * 8 + tq * 2 + (j & 1);
                    int row = qt * 128 + w * 16 + r0 + ((j >> 1) ? 8 : 0);
                    if (col > row) v = -1e9f;
                }
                sc[nt][j] = v;
            }
        }
        float rm0 = -1e30f, rm1 = -1e30f;
        #pragma unroll
        for (int nt = 0; nt < 8; nt++) {
            rm0 = fmaxf(rm0, fmaxf(sc[nt][0], sc[nt][1]));
            rm1 = fmaxf(rm1, fmaxf(sc[nt][2], sc[nt][3]));
        }
        #pragma unroll
        for (int off = 1; off < 4; off <<= 1) {
            rm0 = fmaxf(rm0, __shfl_xor_sync(0xffffffffu, rm0, off));
            rm1 = fmaxf(rm1, __shfl_xor_sync(0xffffffffu, rm1, off));
        }
        float mn0 = fmaxf(m0, rm0), mn1 = fmaxf(m1, rm1);
        float al0 = __expf(m0 - mn0), al1 = __expf(m1 - mn1);
        m0 = mn0; m1 = mn1;
        float rs0 = 0.0f, rs1 = 0.0f;
        #pragma unroll
        for (int nt = 0; nt < 8; nt++) {
            sc[nt][0] = __expf(sc[nt][0] - mn0);
            sc[nt][1] = __expf(sc[nt][1] - mn0);
            sc[nt][2] = __expf(sc[nt][2] - mn1);
            sc[nt][3] = __expf(sc[nt][3] - mn1);
            rs0 += sc[nt][0] + sc[nt][1];
            rs1 += sc[nt][2] + sc[nt][3];
        }
        #pragma unroll
        for (int off = 1; off < 4; off <<= 1) {
            rs0 += __shfl_xor_sync(0xffffffffu, rs0, off);
            rs1 += __shfl_xor_sync(0xffffffffu, rs1, off);
        }
        l0 = l0 * al0 + rs0;
        l1 = l1 * al1 + rs1;
        #pragma unroll
        for (int nt = 0; nt < 8; nt++) {
            o[nt][0] *= al0; o[nt][1] *= al0;
            o[nt][2] *= al1; o[nt][3] *= al1;
        }
        #pragma unroll
        for (int kp = 0; kp < 4; kp++) {
            unsigned pah[4], pal[4];
            {
                float x0 = sc[2*kp][0],   x1 = sc[2*kp][1];
                float x2 = sc[2*kp][2],   x3 = sc[2*kp][3];
                float y0 = sc[2*kp+1][0], y1 = sc[2*kp+1][1];
                float y2 = sc[2*kp+1][2], y3 = sc[2*kp+1][3];
                pah[0] = pk2(x0, x1); pah[1] = pk2(x2, x3);
                pah[2] = pk2(y0, y1); pah[3] = pk2(y2, y3);
                pal[0] = pk2(x0 - bfrt(x0), x1 - bfrt(x1));
                pal[1] = pk2(x2 - bfrt(x2), x3 - bfrt(x3));
                pal[2] = pk2(y0 - bfrt(y0), y1 - bfrt(y1));
                pal[3] = pk2(y2 - bfrt(y2), y3 - bfrt(y3));
            }
            #pragma unroll
            for (int nt = 0; nt < 8; nt++) {
                int drow = nt * 8 + r0;
                int c = kp * 16 + tq * 2;
                unsigned bh[2], bl[2];
                bh[0] = *(const unsigned*)&Vth[drow][c];
                bh[1] = *(const unsigned*)&Vth[drow][c + 8];
                bl[0] = *(const unsigned*)&Vtl[drow][c];
                bl[1] = *(const unsigned*)&Vtl[drow][c + 8];
                mma16816(o[nt], pah, bh);
                mma16816(o[nt], pah, bl);
                mma16816(o[nt], pal, bh);
            }
        }
    }
    float inv0 = 1.0f / l0, inv1 = 1.0f / l1;
    size_t base0 = ((size_t)(b * NN + qrow)) * CC + h * DD;
    size_t base1 = ((size_t)(b * NN + qrow + 8)) * CC + h * DD;
    #pragma unroll
    for (int nt = 0; nt < 8; nt++) {
        int d = nt * 8 + tq * 2;
        float v0 = o[nt][0] * inv0, v1 = o[nt][1] * inv0;
        float v2 = o[nt][2] * inv1, v3 = o[nt][3] * inv1;
        *(unsigned*)(ohi + base0 + d) = pk2(bfrt(v0), bfrt(v1));
        *(unsigned*)(olo + base0 + d) = pk2(v0 - bfrt(v0), v1 - bfrt(v1));
        *(unsigned*)(ohi + base1 + d) = pk2(bfrt(v2), bfrt(v3));
        *(unsigned*)(olo + base1 + d) = pk2(v2 - bfrt(v2), v3 - bfrt(v3));
    }
}

// ---------------- MoE routing ----------------
__global__ void zero_kernel() {
    int t = threadIdx.x;
    if (t < EE) { g_count[t] = 0; g_Psum[t] = 0.0f; }
}

__global__ void router_kernel(const float* __restrict__ rw, const float* __restrict__ rb) {
    __shared__ float sP[EE];
    int tid = threadIdx.x;
    if (tid < EE) sP[tid] = 0.0f;
    __syncthreads();
    int t = blockIdx.x * blockDim.x + tid;
    float logit[EE];
    const float* hrow = g_h + (size_t)t * CC;
    #pragma unroll
    for (int e = 0; e < EE; e++) logit[e] = rb[e];
    for (int k = 0; k < CC; k++) {
        float hv = hrow[k];
        const float* wr = rw + k * EE;
        #pragma unroll
        for (int e = 0; e < EE; e++) logit[e] += hv * wr[e];
    }
    float mx = logit[0];
    #pragma unroll
    for (int e = 1; e < EE; e++) mx = fmaxf(mx, logit[e]);
    float p[EE], ps = 0.0f;
    #pragma unroll
    for (int e = 0; e < EE; e++) { p[e] = __expf(logit[e] - mx); ps += p[e]; }
    float invs = 1.0f / ps;
    #pragma unroll
    for (int e = 0; e < EE; e++) p[e] *= invs;
    int i0 = 0;
    #pragma unroll
    for (int e = 1; e < EE; e++) if (p[e] > p[i0]) i0 = e;
    int i1 = (i0 == 0) ? 1 : 0;
    #pragma unroll
    for (int e = 0; e < EE; e++) if (e != i0 && p[e] > p[i1]) i1 = e;
    float gs = p[i0] + p[i1];
    float g0 = p[i0] / gs, g1 = p[i1] / gs;
    int s0 = atomicAdd(&g_count[i0], 1);
    int s1 = atomicAdd(&g_count[i1], 1);
    int r0 = i0 * EROWS + s0, r1 = i1 * EROWS + s1;
    g_tok_of_row[r0] = t; g_tok_of_row[r1] = t;
    g_tokrow[t * 2] = r0; g_tokrow[t * 2 + 1] = r1;
    g_tokgate[t * 2] = g0; g_tokgate[t * 2 + 1] = g1;
    #pragma unroll
    for (int e = 0; e < EE; e++) atomicAdd(&sP[e], p[e]);
    __syncthreads();
    if (tid < EE) atomicAdd(&g_Psum[tid], sP[tid]);
}

// ---------------- expert GEMM 1 (gathered A, GELU -> mid hi/lo) ----------------
__global__ void __launch_bounds__(256) egemm1_kernel(const float* __restrict__ eb1) {
    int e = blockIdx.z;
    int cnt = g_count[e];
    int row0 = blockIdx.y * 128;
    if (row0 >= cnt) return;
    int col0 = blockIdx.x * 128;
    extern __shared__ char smraw[];
    SmemGemm* S = (SmemGemm*)smraw;
    float (*Cs)[CPAD] = (float(*)[CPAD])smraw;
    __shared__ int s_tok[128];
    int tid = threadIdx.x;
    if (tid < 128) {
        int gr = row0 + tid;
        s_tok[tid] = (gr < cnt) ? g_tok_of_row[e * EROWS + gr] : -1;
    }
    __syncthreads();
    AccFrag acc[2][4];
    #pragma unroll
    for (int i = 0; i < 2; i++)
        #pragma unroll
        for (int j = 0; j < 4; j++) wmma::fill_fragment(acc[i][j], 0.0f);
    size_t woff = OFF_EW1 + (size_t)e * CC * FF;
    wmma_core(g_h_hi, g_h_lo, g_w_hi + woff, g_w_lo + woff, s_tok, 0, FF, CC, 0, col0, S, acc);
    stage_acc(acc, Cs, tid);
    #pragma unroll
    for (int u = 0; u < 16; u++) {
        int f = tid + u * 256;
        int r = f >> 5, c = (f & 31) * 4;
        if (row0 + r >= cnt) continue;
        int gc = col0 + c;
        float4 v = *(float4*)&Cs[r][c];
        float vv[4] = {v.x, v.y, v.z, v.w};
        __align__(8) __nv_bfloat16 hh[4], ll[4];
        #pragma unroll
        for (int j = 0; j < 4; j++) {
            float xx = vv[j] + eb1[e * FF + gc + j];
            float uu = 0.7978845608028654f * (xx + 0.044715f * xx * xx * xx);
            float ge = 0.5f * xx * (1.0f + tanhf(uu));
            split1(ge, hh[j], ll[j]);
        }
        size_t idx = ((size_t)e * EROWS + row0 + r) * FF + gc;
        *(uint2*)(g_mid_hi + idx) = *(uint2*)hh;
        *(uint2*)(g_mid_lo + idx) = *(uint2*)ll;
    }
}

// ---------------- expert GEMM 2 ----------------
__global__ void __launch_bounds__(256) egemm2_kernel(const float* __restrict__ eb2) {
    int e = blockIdx.z;
    int cnt = g_count[e];
    int row0 = blockIdx.y * 128;
    if (row0 >= cnt) return;
    int col0 = blockIdx.x * 128;
    extern __shared__ char smraw[];
    SmemGemm* S = (SmemGemm*)smraw;
    float (*Cs)[CPAD] = (float(*)[CPAD])smraw;
    int tid = threadIdx.x;
    AccFrag acc[2][4];
    #pragma unroll
    for (int i = 0; i < 2; i++)
        #pragma unroll
        for (int j = 0; j < 4; j++) wmma::fill_fragment(acc[i][j], 0.0f);
    size_t woff = OFF_EW2 + (size_t)e * FF * CC;
    wmma_core(g_mid_hi + (size_t)e * EROWS * FF, g_mid_lo + (size_t)e * EROWS * FF,
              g_w_hi + woff, g_w_lo + woff, nullptr, cnt, CC, FF, row0, col0, S, acc);
    stage_acc(acc, Cs, tid);
    #pragma unroll
    for (int u = 0; u < 16; u++) {
        int f = tid + u * 256;
        int r = f >> 5, c = (f & 31) * 4;
        if (row0 + r >= cnt) continue;
        int gc = col0 + c;
        float4 v = *(float4*)&Cs[r][c];
        v.x += eb2[e * CC + gc];     v.y += eb2[e * CC + gc + 1];
        v.z += eb2[e * CC + gc + 2]; v.w += eb2[e * CC + gc + 3];
        *(float4*)&g_eo[((size_t)e * EROWS + row0 + r) * CC + gc] = v;
    }
}

// ---------------- combine + aux ----------------
__global__ void combine_kernel(float* __restrict__ out) {
    int t = blockIdx.x;
    int tid = threadIdx.x;
    int r0 = g_tokrow[t * 2], r1 = g_tokrow[t * 2 + 1];
    float g0 = g_tokgate[t * 2], g1 = g_tokgate[t * 2 + 1];
    const float* x2 = g_x2 + (size_t)t * CC;
    const float* e0 = g_eo + (size_t)r0 * CC;
    const float* e1 = g_eo + (size_t)r1 * CC;
    float* orow = out + (size_t)t * CC;
    for (int c = tid; c < CC; c += 128)
        orow[c] = x2[c] + g0 * e0[c] + g1 * e1[c];
}

__global__ void aux_kernel(float* __restrict__ out, int out_size) {
    if (threadIdx.x == 0 && blockIdx.x == 0) {
        float a = 0.0f;
        for (int e = 0; e < EE; e++)
            a += (g_count[e] / (float)TOK) * (g_Psum[e] / (float)TOK);
        a *= (float)EE;
        if (out_size > TOK * CC) out[TOK * CC] = a;
    }
}

// ---------------- launch ----------------
extern "C" void kernel_launch(void* const* d_in, const int* in_sizes, int n_in,
                              void* d_out, int out_size) {
    const float* x      = (const float*)d_in[0];
    const float* vision = (const float*)d_in[1];
    const float* ln1_g = (const float*)d_in[2];  const float* ln1_b = (const float*)d_in[3];
    const float* ln2_g = (const float*)d_in[4];  const float* ln2_b = (const float*)d_in[5];
    const float* ln3_g = (const float*)d_in[6];  const float* ln3_b = (const float*)d_in[7];
    const float* sa_wq = (const float*)d_in[8];  const float* sa_bq = (const float*)d_in[9];
    const float* sa_wk = (const float*)d_in[10]; const float* sa_bk = (const float*)d_in[11];
    const float* sa_wv = (const float*)d_in[12]; const float* sa_bv = (const float*)d_in[13];
    const float* sa_wo = (const float*)d_in[14]; const float* sa_bo = (const float*)d_in[15];
    const float* ca_wq = (const float*)d_in[16]; const float* ca_bq = (const float*)d_in[17];
    const float* ca_wk = (const float*)d_in[18]; const float* ca_bk = (const float*)d_in[19];
    const float* ca_wv = (const float*)d_in[20]; const float* ca_bv = (const float*)d_in[21];
    const float* ca_wo = (const float*)d_in[22]; const float* ca_bo = (const float*)d_in[23];
    const float* rw    = (const float*)d_in[24]; const float* rb    = (const float*)d_in[25];
    const float* ew1   = (const float*)d_in[26]; const float* eb1   = (const float*)d_in[27];
    const float* ew2   = (const float*)d_in[28]; const float* eb2   = (const float*)d_in[29];
    float* out = (float*)d_out;

    float *p_h, *p_x1, *p_x2;
    __nv_bfloat16 *p_hh, *p_hl, *p_qh, *p_ql, *p_kh, *p_kl, *p_vh_, *p_vl_;
    __nv_bfloat16 *p_ath, *p_atl, *p_vih, *p_vil, *p_wh, *p_wl;
    cudaGetSymbolAddress((void**)&p_h,  g_h);
    cudaGetSymbolAddress((void**)&p_x1, g_x1);
    cudaGetSymbolAddress((void**)&p_x2, g_x2);
    cudaGetSymbolAddress((void**)&p_hh, g_h_hi);
    cudaGetSymbolAddress((void**)&p_hl, g_h_lo);
    cudaGetSymbolAddress((void**)&p_qh, g_q_hi);
    cudaGetSymbolAddress((void**)&p_ql, g_q_lo);
    cudaGetSymbolAddress((void**)&p_kh, g_k_hi);
    cudaGetSymbolAddress((void**)&p_kl, g_k_lo);
    cudaGetSymbolAddress((void**)&p_vh_, g_v_hi);
    cudaGetSymbolAddress((void**)&p_vl_, g_v_lo);
    cudaGetSymbolAddress((void**)&p_ath, g_att_hi);
    cudaGetSymbolAddress((void**)&p_atl, g_att_lo);
    cudaGetSymbolAddress((void**)&p_vih, g_vis_hi);
    cudaGetSymbolAddress((void**)&p_vil, g_vis_lo);
    cudaGetSymbolAddress((void**)&p_wh, g_w_hi);
    cudaGetSymbolAddress((void**)&p_wl, g_w_lo);

    const int gemm_smem = GEMM_SMEM_BYTES;
    cudaFuncSetAttribute(gemm128,       cudaFuncAttributeMaxDynamicSharedMemorySize, gemm_smem);
    cudaFuncSetAttribute(kvgemm128,     cudaFuncAttributeMaxDynamicSharedMemorySize, gemm_smem);
    cudaFuncSetAttribute(egemm1_kernel, cudaFuncAttributeMaxDynamicSharedMemorySize, gemm_smem);
    cudaFuncSetAttribute(egemm2_kernel, cudaFuncAttributeMaxDynamicSharedMemorySize, gemm_smem);

    // --- weight + vision conversion ---
    auto conv = [&](const float* src, size_t off, int n) {
        conv_kernel<<<(n / 4 + 255) / 256, 256>>>(src, p_wh + off, p_wl + off, n);
    };
    conv(sa_wq, OFF_SAWQ, SZ_QO); conv(sa_wk, OFF_SAWK, SZ_KV);
    conv(sa_wv, OFF_SAWV, SZ_KV); conv(sa_wo, OFF_SAWO, SZ_QO);
    conv(ca_wq, OFF_CAWQ, SZ_QO); conv(ca_wk, OFF_CAWK, SZ_KV);
    conv(ca_wv, OFF_CAWV, SZ_KV); conv(ca_wo, OFF_CAWO, SZ_QO);
    conv(ew1, OFF_EW1, EE * CC * FF);
    conv(ew2, OFF_EW2, EE * FF * CC);
    conv_kernel<<<(BB * MV * CC / 4 + 255) / 256, 256>>>(vision, p_vih, p_vil, BB * MV * CC);

    dim3 gC(CC / 128, TOK / 128);
    dim3 gKVsa(2, TOK / 128);
    dim3 gKVca(2, (BB * MV) / 128);
    dim3 gAtt(NN / 128, HH, BB);

    // --- block 1: pre-norm causal GQA self-attn + residual ---
    ln_kernel<<<TOK, 256>>>(x, ln1_g, ln1_b, p_h, p_hh, p_hl);
    gemm128<<<gC, 256, gemm_smem>>>(p_hh, p_hl, OFF_SAWQ, sa_bq, nullptr,
                                    nullptr, p_qh, p_ql, TOK, CC, CC);
    kvgemm128<<<gKVsa, 256, gemm_smem>>>(p_hh, p_hl, OFF_SAWK, sa_bk, OFF_SAWV, sa_bv,
                                         p_kh, p_kl, p_vh_, p_vl_, TOK, CC);
    flash_mma<<<gAtt, 256>>>(p_qh, p_ql, p_kh, p_kl, p_vh_, p_vl_, p_ath, p_atl, NN, 1);
    gemm128<<<gC, 256, gemm_smem>>>(p_ath, p_atl, OFF_SAWO, sa_bo, x,
                                    p_x1, nullptr, nullptr, TOK, CC, CC);

    // --- block 2: pre-norm cross-attn + residual ---
    ln_kernel<<<TOK, 256>>>(p_x1, ln2_g, ln2_b, p_h, p_hh, p_hl);
    gemm128<<<gC, 256, gemm_smem>>>(p_hh, p_hl, OFF_CAWQ, ca_bq, nullptr,
                                    nullptr, p_qh, p_ql, TOK, CC, CC);
    kvgemm128<<<gKVca, 256, gemm_smem>>>(p_vih, p_vil, OFF_CAWK, ca_bk, OFF_CAWV, ca_bv,
                                         p_kh, p_kl, p_vh_, p_vl_, BB * MV, CC);
    flash_mma<<<gAtt, 256>>>(p_qh, p_ql, p_kh, p_kl, p_vh_, p_vl_, p_ath, p_atl, MV, 0);
    gemm128<<<gC, 256, gemm_smem>>>(p_ath, p_atl, OFF_CAWO, ca_bo, p_x1,
                                    p_x2, nullptr, nullptr, TOK, CC, CC);

    // --- block 3: pre-norm MoE + residual ---
    ln_kernel<<<TOK, 256>>>(p_x2, ln3_g, ln3_b, p_h, p_hh, p_hl);
    zero_kernel<<<1, 32>>>();
    router_kernel<<<TOK / 256, 256>>>(rw, rb);
    egemm1_kernel<<<dim3(FF / 128, EROWS / 128, EE), 256, gemm_smem>>>(eb1);
    egemm2_kernel<<<dim3(CC / 128, EROWS / 128, EE), 256, gemm_smem>>>(eb2);
    combine_kernel<<<TOK, 128>>>(out);
    aux_kernel<<<1, 1>>>(out, out_size);
}

// round 13
// speedup vs baseline: 1.0213x; 1.0213x over previous
#include <cuda_runtime.h>
#include <cuda_bf16.h>
#include <mma.h>
#include <math.h>
#include <cstdint>

using namespace nvcuda;

// ---------------- problem constants ----------------
#define BB 4
#define NN 2048
#define MV 576
#define CC 512
#define HH 8
#define KVH 2
#define DD 64
#define EE 8
#define TOPK 2
#define FF 2048
#define TOK (BB*NN)
#define KVDIM (KVH*DD)       // 128
#define EROWS 8192

// weight buffer offsets (elements)
#define SZ_QO (CC*CC)
#define SZ_KV (CC*KVDIM)
#define OFF_SAWQ 0
#define OFF_SAWK (OFF_SAWQ+SZ_QO)
#define OFF_SAWV (OFF_SAWK+SZ_KV)
#define OFF_SAWO (OFF_SAWV+SZ_KV)
#define OFF_CAWQ (OFF_SAWO+SZ_QO)
#define OFF_CAWK (OFF_CAWQ+SZ_QO)
#define OFF_CAWV (OFF_CAWK+SZ_KV)
#define OFF_CAWO (OFF_CAWV+SZ_KV)
#define OFF_EW1  (OFF_CAWO+SZ_QO)
#define OFF_EW2  (OFF_EW1 + (size_t)EE*CC*FF)
#define WTOT     (OFF_EW2 + (size_t)EE*FF*CC)

// ---------------- static scratch ----------------
__device__ float g_h  [(size_t)TOK*CC];     // fp32 LN out (router)
__device__ float g_x1 [(size_t)TOK*CC];
__device__ float g_x2 [(size_t)TOK*CC];
__device__ float g_eo [(size_t)EE*EROWS*CC];
__device__ __nv_bfloat16 g_h_hi [(size_t)TOK*CC];
__device__ __nv_bfloat16 g_h_lo [(size_t)TOK*CC];
__device__ __nv_bfloat16 g_q_hi [(size_t)TOK*CC];
__device__ __nv_bfloat16 g_q_lo [(size_t)TOK*CC];
__device__ __nv_bfloat16 g_k_hi [(size_t)TOK*KVDIM];
__device__ __nv_bfloat16 g_k_lo [(size_t)TOK*KVDIM];
__device__ __nv_bfloat16 g_v_hi [(size_t)TOK*KVDIM];
__device__ __nv_bfloat16 g_v_lo [(size_t)TOK*KVDIM];
// dedicated CA K/V (produced early on side stream; must not alias SA K/V)
__device__ __nv_bfloat16 g_k2_hi[(size_t)BB*MV*KVDIM];
__device__ __nv_bfloat16 g_k2_lo[(size_t)BB*MV*KVDIM];
__device__ __nv_bfloat16 g_v2_hi[(size_t)BB*MV*KVDIM];
__device__ __nv_bfloat16 g_v2_lo[(size_t)BB*MV*KVDIM];
__device__ __nv_bfloat16 g_att_hi[(size_t)TOK*CC];
__device__ __nv_bfloat16 g_att_lo[(size_t)TOK*CC];
__device__ __nv_bfloat16 g_vis_hi[(size_t)BB*MV*CC];
__device__ __nv_bfloat16 g_vis_lo[(size_t)BB*MV*CC];
__device__ __nv_bfloat16 g_mid_hi[(size_t)EE*EROWS*FF];
__device__ __nv_bfloat16 g_mid_lo[(size_t)EE*EROWS*FF];
__device__ __nv_bfloat16 g_w_hi[WTOT];
__device__ __nv_bfloat16 g_w_lo[WTOT];
__device__ int   g_count[EE];
__device__ float g_Psum[EE];
__device__ int   g_tokrow [TOK*TOPK];
__device__ float g_tokgate[TOK*TOPK];
__device__ int   g_tok_of_row[EE*EROWS];

// ---------------- helpers ----------------
__device__ __forceinline__ void split1(float v, __nv_bfloat16& h, __nv_bfloat16& l) {
    h = __float2bfloat16(v);
    l = __float2bfloat16(v - __bfloat162float(h));
}
__device__ __forceinline__ unsigned pk2(float lo, float hi) {
    unsigned r;
    asm("cvt.rn.bf16x2.f32 %0, %1, %2;" : "=r"(r) : "f"(hi), "f"(lo));
    return r;
}
__device__ __forceinline__ float bfrt(float x) {
    return __bfloat162float(__float2bfloat16(x));
}
__device__ __forceinline__ void mma16816(float* c, const unsigned* a, const unsigned* b) {
    asm volatile(
        "mma.sync.aligned.m16n8k16.row.col.f32.bf16.bf16.f32 "
        "{%0,%1,%2,%3},{%4,%5,%6,%7},{%8,%9},{%0,%1,%2,%3};"
        : "+f"(c[0]), "+f"(c[1]), "+f"(c[2]), "+f"(c[3])
        : "r"(a[0]), "r"(a[1]), "r"(a[2]), "r"(a[3]), "r"(b[0]), "r"(b[1]));
}
// 16B async copy; zero-fill when !valid
__device__ __forceinline__ void cp16(void* dst, const void* src, bool valid) {
    unsigned d = (unsigned)__cvta_generic_to_shared(dst);
    int sz = valid ? 16 : 0;
    asm volatile("cp.async.cg.shared.global [%0], [%1], 16, %2;\n" :: "r"(d), "l"(src), "r"(sz));
}
#define CP_COMMIT asm volatile("cp.async.commit_group;\n" ::: "memory")
#define CP_WAIT0  asm volatile("cp.async.wait_group 0;\n" ::: "memory")
#define CP_WAIT1  asm volatile("cp.async.wait_group 1;\n" ::: "memory")

// ---------------- fp32 -> hi/lo bf16 conversion ----------------
__global__ void conv_kernel(const float* __restrict__ src, __nv_bfloat16* __restrict__ hi,
                            __nv_bfloat16* __restrict__ lo, int n) {
    int i = (blockIdx.x * blockDim.x + threadIdx.x) * 4;
    if (i >= n) return;
    float4 v = *(const float4*)(src + i);
    __align__(8) __nv_bfloat16 h[4], l[4];
    split1(v.x, h[0], l[0]); split1(v.y, h[1], l[1]);
    split1(v.z, h[2], l[2]); split1(v.w, h[3], l[3]);
    *(uint2*)(hi + i) = *(uint2*)h;
    *(uint2*)(lo + i) = *(uint2*)l;
}

// ---------------- LayerNorm (fp32 + hi/lo bf16 out) ----------------
__global__ void ln_kernel(const float* __restrict__ x, const float* __restrict__ g,
                          const float* __restrict__ b, float* __restrict__ o,
                          __nv_bfloat16* __restrict__ ohi, __nv_bfloat16* __restrict__ olo) {
    int t = blockIdx.x;
    int tid = threadIdx.x;
    const float* xr = x + (size_t)t * CC;
    float v0 = xr[tid], v1 = xr[tid + 256];
    __shared__ float red[256];
    red[tid] = v0 + v1; __syncthreads();
    for (int off = 128; off > 0; off >>= 1) {
        if (tid < off) red[tid] += red[tid + off];
        __syncthreads();
    }
    float mu = red[0] * (1.0f / CC);
    __syncthreads();
    float d0 = v0 - mu, d1 = v1 - mu;
    red[tid] = d0 * d0 + d1 * d1; __syncthreads();
    for (int off = 128; off > 0; off >>= 1) {
        if (tid < off) red[tid] += red[tid + off];
        __syncthreads();
    }
    float rstd = rsqrtf(red[0] * (1.0f / CC) + 1e-6f);
    size_t base = (size_t)t * CC;
    float r0 = d0 * rstd * g[tid]       + b[tid];
    float r1 = d1 * rstd * g[tid + 256] + b[tid + 256];
    o[base + tid] = r0; o[base + tid + 256] = r1;
    __nv_bfloat16 h, l;
    split1(r0, h, l); ohi[base + tid] = h;       olo[base + tid] = l;
    split1(r1, h, l); ohi[base + tid + 256] = h; olo[base + tid + 256] = l;
}

// ---------------- wmma split-bf16 GEMM core, 2-stage cp.async pipeline ----------------
#define APAD 40
#define BPAD 136
#define CPAD 132
struct SmemGemm {
    __nv_bfloat16 Ah[2][128][APAD];
    __nv_bfloat16 Al[2][128][APAD];
    __nv_bfloat16 Bh[2][32][BPAD];
    __nv_bfloat16 Bl[2][32][BPAD];
};
#define GEMM_SMEM_BYTES 75776

typedef wmma::fragment<wmma::accumulator, 16, 16, 16, float> AccFrag;

__device__ __forceinline__ void wmma_core(
        const __nv_bfloat16* __restrict__ Ahg, const __nv_bfloat16* __restrict__ Alg,
        const __nv_bfloat16* __restrict__ Bhg, const __nv_bfloat16* __restrict__ Blg,
        const int* __restrict__ tokidx,
        int Mr, int Nc, int Kd, int row0, int col0,
        SmemGemm* S, AccFrag (&acc)[2][4]) {
    int tid = threadIdx.x;
    int w = tid >> 5, wm = w & 3, wn = w >> 2;
    int ra = tid >> 1, kc = (tid & 1) * 16;
    int rb = tid >> 3, cb = (tid & 7) * 16;

    size_t arow; bool avalid;
    if (tokidx) {
        int tok = tokidx[ra];
        avalid = (tok >= 0);
        arow = (size_t)(avalid ? tok : 0) * Kd;
    } else {
        int gr = row0 + ra;
        avalid = (gr < Mr);
        arow = (size_t)(avalid ? gr : 0) * Kd;
    }

    int nch = Kd / 32;
    auto issue = [&](int c) {
        int k0 = c * 32, buf = c & 1;
        size_t ab = arow + k0 + kc;
        cp16(&S->Ah[buf][ra][kc],     Ahg + ab,     avalid);
        cp16(&S->Ah[buf][ra][kc + 8], Ahg + ab + 8, avalid);
        cp16(&S->Al[buf][ra][kc],     Alg + ab,     avalid);
        cp16(&S->Al[buf][ra][kc + 8], Alg + ab + 8, avalid);
        size_t bb = (size_t)(k0 + rb) * Nc + col0 + cb;
        cp16(&S->Bh[buf][rb][cb],     Bhg + bb,     true);
        cp16(&S->Bh[buf][rb][cb + 8], Bhg + bb + 8, true);
        cp16(&S->Bl[buf][rb][cb],     Blg + bb,     true);
        cp16(&S->Bl[buf][rb][cb + 8], Blg + bb + 8, true);
        CP_COMMIT;
    };

    issue(0);
    #pragma unroll 1
    for (int c = 0; c < nch; c++) {
        if (c + 1 < nch) { issue(c + 1); CP_WAIT1; } else { CP_WAIT0; }
        __syncthreads();
        int buf = c & 1;
        #pragma unroll
        for (int ks = 0; ks < 2; ks++) {
            wmma::fragment<wmma::matrix_a, 16,16,16, __nv_bfloat16, wmma::row_major> ah[2], al[2];
            wmma::fragment<wmma::matrix_b, 16,16,16, __nv_bfloat16, wmma::row_major> bh[4], bl[4];
            #pragma unroll
            for (int i = 0; i < 2; i++) {
                wmma::load_matrix_sync(ah[i], &S->Ah[buf][wm*32 + i*16][ks*16], APAD);
                wmma::load_matrix_sync(al[i], &S->Al[buf][wm*32 + i*16][ks*16], APAD);
            }
            #pragma unroll
            for (int j = 0; j < 4; j++) {
                wmma::load_matrix_sync(bh[j], &S->Bh[buf][ks*16][wn*64 + j*16], BPAD);
                wmma::load_matrix_sync(bl[j], &S->Bl[buf][ks*16][wn*64 + j*16], BPAD);
            }
            #pragma unroll
            for (int i = 0; i < 2; i++)
                #pragma unroll
                for (int j = 0; j < 4; j++) {
                    wmma::mma_sync(acc[i][j], ah[i], bh[j], acc[i][j]);
                    wmma::mma_sync(acc[i][j], ah[i], bl[j], acc[i][j]);
                    wmma::mma_sync(acc[i][j], al[i], bh[j], acc[i][j]);
                }
        }
        __syncthreads();
    }
}

__device__ __forceinline__ void stage_acc(AccFrag (&acc)[2][4], float (*Cs)[CPAD], int tid) {
    int w = tid >> 5, wm = w & 3, wn = w >> 2;
    #pragma unroll
    for (int i = 0; i < 2; i++)
        #pragma unroll
        for (int j = 0; j < 4; j++)
            wmma::store_matrix_sync(&Cs[wm*32 + i*16][wn*64 + j*16], acc[i][j],
                                    CPAD, wmma::mem_row_major);
    __syncthreads();
}

// ---------------- generic GEMM: fp32 out (bias/resid) OR hi/lo bf16 out ----------------
__global__ void __launch_bounds__(256) gemm128(
        const __nv_bfloat16* __restrict__ Ahg, const __nv_bfloat16* __restrict__ Alg,
        int woff, const float* __restrict__ bias, const float* __restrict__ resid,
        float* __restrict__ out,
        __nv_bfloat16* __restrict__ ohi, __nv_bfloat16* __restrict__ olo,
        int Mr, int Nc, int Kd) {
    extern __shared__ char smraw[];
    SmemGemm* S = (SmemGemm*)smraw;
    float (*Cs)[CPAD] = (float(*)[CPAD])smraw;
    int tid = threadIdx.x;
    int row0 = blockIdx.y * 128, col0 = blockIdx.x * 128;
    AccFrag acc[2][4];
    #pragma unroll
    for (int i = 0; i < 2; i++)
        #pragma unroll
        for (int j = 0; j < 4; j++) wmma::fill_fragment(acc[i][j], 0.0f);
    wmma_core(Ahg, Alg, g_w_hi + woff, g_w_lo + woff, nullptr, Mr, Nc, Kd, row0, col0, S, acc);
    stage_acc(acc, Cs, tid);
    #pragma unroll
    for (int u = 0; u < 16; u++) {
        int f = tid + u * 256;
        int r = f >> 5, c = (f & 31) * 4;
        int gr = row0 + r;
        if (gr >= Mr) continue;
        int gc = col0 + c;
        float4 v = *(float4*)&Cs[r][c];
        if (bias) { v.x += bias[gc]; v.y += bias[gc+1]; v.z += bias[gc+2]; v.w += bias[gc+3]; }
        if (resid) {
            float4 rr = *(const float4*)(resid + (size_t)gr * Nc + gc);
            v.x += rr.x; v.y += rr.y; v.z += rr.z; v.w += rr.w;
        }
        if (out) {
            *(float4*)(out + (size_t)gr * Nc + gc) = v;
        } else {
            __align__(8) __nv_bfloat16 hh[4], ll[4];
            split1(v.x, hh[0], ll[0]); split1(v.y, hh[1], ll[1]);
            split1(v.z, hh[2], ll[2]); split1(v.w, hh[3], ll[3]);
            *(uint2*)(ohi + (size_t)gr * Nc + gc) = *(uint2*)hh;
            *(uint2*)(olo + (size_t)gr * Nc + gc) = *(uint2*)ll;
        }
    }
}

// ---------------- fused K+V projection -> hi/lo bf16 ----------------
__global__ void __launch_bounds__(256) kvgemm128(
        const __nv_bfloat16* __restrict__ Ahg, const __nv_bfloat16* __restrict__ Alg,
        int woffk, const float* __restrict__ bk,
        int woffv, const float* __restrict__ bv,
        __nv_bfloat16* __restrict__ okh, __nv_bfloat16* __restrict__ okl,
        __nv_bfloat16* __restrict__ ovh, __nv_bfloat16* __restrict__ ovl,
        int Mr, int Kd) {
    extern __shared__ char smraw[];
    SmemGemm* S = (SmemGemm*)smraw;
    float (*Cs)[CPAD] = (float(*)[CPAD])smraw;
    int woff          = (blockIdx.x == 0) ? woffk : woffv;
    const float* bias = (blockIdx.x == 0) ? bk : bv;
    __nv_bfloat16* oh = (blockIdx.x == 0) ? okh : ovh;
    __nv_bfloat16* ol = (blockIdx.x == 0) ? okl : ovl;
    int tid = threadIdx.x;
    int row0 = blockIdx.y * 128;
    AccFrag acc[2][4];
    #pragma unroll
    for (int i = 0; i < 2; i++)
        #pragma unroll
        for (int j = 0; j < 4; j++) wmma::fill_fragment(acc[i][j], 0.0f);
    wmma_core(Ahg, Alg, g_w_hi + woff, g_w_lo + woff, nullptr, Mr, KVDIM, Kd, row0, 0, S, acc);
    stage_acc(acc, Cs, tid);
    #pragma unroll
    for (int u = 0; u < 16; u++) {
        int f = tid + u * 256;
        int r = f >> 5, c = (f & 31) * 4;
        int gr = row0 + r;
        if (gr >= Mr) continue;
        float4 v = *(float4*)&Cs[r][c];
        v.x += bias[c]; v.y += bias[c+1]; v.z += bias[c+2]; v.w += bias[c+3];
        __align__(8) __nv_bfloat16 hh[4], ll[4];
        split1(v.x, hh[0], ll[0]); split1(v.y, hh[1], ll[1]);
        split1(v.z, hh[2], ll[2]); split1(v.w, hh[3], ll[3]);
        *(uint2*)(oh + (size_t)gr * KVDIM + c) = *(uint2*)hh;
        *(uint2*)(ol + (size_t)gr * KVDIM + c) = *(uint2*)ll;
    }
}

// ---------------- FA2 flash attention: mma.m16n8k16 split-bf16 ----------------
#define KPAD 72
__global__ void __launch_bounds__(256) flash_mma(
        const __nv_bfloat16* __restrict__ qhi, const __nv_bfloat16* __restrict__ qlo,
        const __nv_bfloat16* __restrict__ khi, const __nv_bfloat16* __restrict__ klo,
        const __nv_bfloat16* __restrict__ vhi, const __nv_bfloat16* __restrict__ vlo,
        __nv_bfloat16* __restrict__ ohi, __nv_bfloat16* __restrict__ olo,
        int n_kv, int causal) {
    __shared__ __nv_bfloat16 Kh[64][KPAD], Kl[64][KPAD], Vth[64][KPAD], Vtl[64][KPAD];
    int qt = blockIdx.x, h = blockIdx.y, b = blockIdx.z;
    int g = h >> 2;
    int tid = threadIdx.x, w = tid >> 5, lane = tid & 31;
    int r0 = lane >> 2, tq = lane & 3;
    int qrow = qt * 128 + w * 16 + r0;

    unsigned qah[4][4], qal[4][4];
    {
        const __nv_bfloat16* q0h = qhi + ((size_t)(b * NN + qrow)) * CC + h * DD;
        const __nv_bfloat16* q1h = qhi + ((size_t)(b * NN + qrow + 8)) * CC + h * DD;
        const __nv_bfloat16* q0l = qlo + ((size_t)(b * NN + qrow)) * CC + h * DD;
        const __nv_bfloat16* q1l = qlo + ((size_t)(b * NN + qrow + 8)) * CC + h * DD;
        #pragma unroll
        for (int ks = 0; ks < 4; ks++) {
            int c = ks * 16 + tq * 2;
            qah[ks][0] = *(const unsigned*)(q0h + c);
            qah[ks][1] = *(const unsigned*)(q1h + c);
            qah[ks][2] = *(const unsigned*)(q0h + c + 8);
            qah[ks][3] = *(const unsigned*)(q1h + c + 8);
            qal[ks][0] = *(const unsigned*)(q0l + c);
            qal[ks][1] = *(const unsigned*)(q1l + c);
            qal[ks][2] = *(const unsigned*)(q0l + c + 8);
            qal[ks][3] = *(const unsigned*)(q1l + c + 8);
        }
    }

    float m0 = -1e30f, m1 = -1e30f, l0 = 0.0f, l1 = 0.0f;
    float o[8][4] = {};

    int key_l = tid >> 2, dseg = (tid & 3) * 16;
    int nkt = causal ? (2 * qt + 2) : (n_kv / 64);
    for (int kt = 0; kt < nkt; kt++) {
        __syncthreads();
        {
            size_t base = ((size_t)(b * n_kv + kt * 64 + key_l)) * KVDIM + g * DD + dseg;
            *(uint4*)&Kh[key_l][dseg]     = *(const uint4*)(khi + base);
            *(uint4*)&Kh[key_l][dseg + 8] = *(const uint4*)(khi + base + 8);
            *(uint4*)&Kl[key_l][dseg]     = *(const uint4*)(klo + base);
            *(uint4*)&Kl[key_l][dseg + 8] = *(const uint4*)(klo + base + 8);
            const __nv_bfloat16* vh = vhi + base;
            const __nv_bfloat16* vl = vlo + base;
            #pragma unroll
            for (int i = 0; i < 16; i++) {
                Vth[dseg + i][key_l] = vh[i];
                Vtl[dseg + i][key_l] = vl[i];
            }
        }
        __syncthreads();

        float sc[8][4] = {};
        #pragma unroll
        for (int nt = 0; nt < 8; nt++) {
            int krow = nt * 8 + r0;
            #pragma unroll
            for (int ks = 0; ks < 4; ks++) {
                int c = ks * 16 + tq * 2;
                unsigned bh[2], bl[2];
                bh[0] = *(const unsigned*)&Kh[krow][c];
                bh[1] = *(const unsigned*)&Kh[krow][c + 8];
                bl[0] = *(const unsigned*)&Kl[krow][c];
                bl[1] = *(const unsigned*)&Kl[krow][c + 8];
                mma16816(sc[nt], qah[ks], bh);
                mma16816(sc[nt], qah[ks], bl);
                mma16816(sc[nt], qal[ks], bh);
            }
        }
        bool maskit = causal && (kt >= 2 * qt);
        #pragma unroll
        for (int nt = 0; nt < 8; nt++) {
            #pragma unroll
            for (int j = 0; j < 4; j++) {
                float v = sc[nt][j] * 0.125f;
                if (maskit) {
                    int col = kt * 64 + nt * 8 + tq * 2 + (j & 1);
                    int row = qt * 128 + w * 16 + r0 + ((j >> 1) ? 8 : 0);
                    if (col > row) v = -1e9f;
                }
                sc[nt][j] = v;
            }
        }
        float rm0 = -1e30f, rm1 = -1e30f;
        #pragma unroll
        for (int nt = 0; nt < 8; nt++) {
            rm0 = fmaxf(rm0, fmaxf(sc[nt][0], sc[nt][1]));
            rm1 = fmaxf(rm1, fmaxf(sc[nt][2], sc[nt][3]));
        }
        #pragma unroll
        for (int off = 1; off < 4; off <<= 1) {
            rm0 = fmaxf(rm0, __shfl_xor_sync(0xffffffffu, rm0, off));
            rm1 = fmaxf(rm1, __shfl_xor_sync(0xffffffffu, rm1, off));
        }
        float mn0 = fmaxf(m0, rm0), mn1 = fmaxf(m1, rm1);
        float al0 = __expf(m0 - mn0), al1 = __expf(m1 - mn1);
        m0 = mn0; m1 = mn1;
        float rs0 = 0.0f, rs1 = 0.0f;
        #pragma unroll
        for (int nt = 0; nt < 8; nt++) {
            sc[nt][0] = __expf(sc[nt][0] - mn0);
            sc[nt][1] = __expf(sc[nt][1] - mn0);
            sc[nt][2] = __expf(sc[nt][2] - mn1);
            sc[nt][3] = __expf(sc[nt][3] - mn1);
            rs0 += sc[nt][0] + sc[nt][1];
            rs1 += sc[nt][2] + sc[nt][3];
        }
        #pragma unroll
        for (int off = 1; off < 4; off <<= 1) {
            rs0 += __shfl_xor_sync(0xffffffffu, rs0, off);
            rs1 += __shfl_xor_sync(0xffffffffu, rs1, off);
        }
        l0 = l0 * al0 + rs0;
        l1 = l1 * al1 + rs1;
        #pragma unroll
        for (int nt = 0; nt < 8; nt++) {
            o[nt][0] *= al0; o[nt][1] *= al0;
            o[nt][2] *= al1; o[nt][3] *= al1;
        }
        #pragma unroll
        for (int kp = 0; kp < 4; kp++) {
            unsigned pah[4], pal[4];
            {
                float x0 = sc[2*kp][0],   x1 = sc[2*kp][1];
                float x2 = sc[2*kp][2],   x3 = sc[2*kp][3];
                float y0 = sc[2*kp+1][0], y1 = sc[2*kp+1][1];
                float y2 = sc[2*kp+1][2], y3 = sc[2*kp+1][3];
                pah[0] = pk2(x0, x1); pah[1] = pk2(x2, x3);
                pah[2] = pk2(y0, y1); pah[3] = pk2(y2, y3);
                pal[0] = pk2(x0 - bfrt(x0), x1 - bfrt(x1));
                pal[1] = pk2(x2 - bfrt(x2), x3 - bfrt(x3));
                pal[2] = pk2(y0 - bfrt(y0), y1 - bfrt(y1));
                pal[3] = pk2(y2 - bfrt(y2), y3 - bfrt(y3));
            }
            #pragma unroll
            for (int nt = 0; nt < 8; nt++) {
                int drow = nt * 8 + r0;
                int c = kp * 16 + tq * 2;
                unsigned bh[2], bl[2];
                bh[0] = *(const unsigned*)&Vth[drow][c];
                bh[1] = *(const unsigned*)&Vth[drow][c + 8];
                bl[0] = *(const unsigned*)&Vtl[drow][c];
                bl[1] = *(const unsigned*)&Vtl[drow][c + 8];
                mma16816(o[nt], pah, bh);
                mma16816(o[nt], pah, bl);
                mma16816(o[nt], pal, bh);
            }
        }
    }
    float inv0 = 1.0f / l0, inv1 = 1.0f / l1;
    size_t base0 = ((size_t)(b * NN + qrow)) * CC + h * DD;
    size_t base1 = ((size_t)(b * NN + qrow + 8)) * CC + h * DD;
    #pragma unroll
    for (int nt = 0; nt < 8; nt++) {
        int d = nt * 8 + tq * 2;
        float v0 = o[nt][0] * inv0, v1 = o[nt][1] * inv0;
        float v2 = o[nt][2] * inv1, v3 = o[nt][3] * inv1;
        *(unsigned*)(ohi + base0 + d) = pk2(bfrt(v0), bfrt(v1));
        *(unsigned*)(olo + base0 + d) = pk2(v0 - bfrt(v0), v1 - bfrt(v1));
        *(unsigned*)(ohi + base1 + d) = pk2(bfrt(v2), bfrt(v3));
        *(unsigned*)(olo + base1 + d) = pk2(v2 - bfrt(v2), v3 - bfrt(v3));
    }
}

// ---------------- MoE routing ----------------
__global__ void zero_kernel() {
    int t = threadIdx.x;
    if (t < EE) { g_count[t] = 0; g_Psum[t] = 0.0f; }
}

__global__ void router_kernel(const float* __restrict__ rw, const float* __restrict__ rb) {
    __shared__ float sP[EE];
    int tid = threadIdx.x;
    if (tid < EE) sP[tid] = 0.0f;
    __syncthreads();
    int t = blockIdx.x * blockDim.x + tid;
    float logit[EE];
    const float* hrow = g_h + (size_t)t * CC;
    #pragma unroll
    for (int e = 0; e < EE; e++) logit[e] = rb[e];
    for (int k = 0; k < CC; k++) {
        float hv = hrow[k];
        const float* wr = rw + k * EE;
        #pragma unroll
        for (int e = 0; e < EE; e++) logit[e] += hv * wr[e];
    }
    float mx = logit[0];
    #pragma unroll
    for (int e = 1; e < EE; e++) mx = fmaxf(mx, logit[e]);
    float p[EE], ps = 0.0f;
    #pragma unroll
    for (int e = 0; e < EE; e++) { p[e] = __expf(logit[e] - mx); ps += p[e]; }
    float invs = 1.0f / ps;
    #pragma unroll
    for (int e = 0; e < EE; e++) p[e] *= invs;
    int i0 = 0;
    #pragma unroll
    for (int e = 1; e < EE; e++) if (p[e] > p[i0]) i0 = e;
    int i1 = (i0 == 0) ? 1 : 0;
    #pragma unroll
    for (int e = 0; e < EE; e++) if (e != i0 && p[e] > p[i1]) i1 = e;
    float gs = p[i0] + p[i1];
    float g0 = p[i0] / gs, g1 = p[i1] / gs;
    int s0 = atomicAdd(&g_count[i0], 1);
    int s1 = atomicAdd(&g_count[i1], 1);
    int r0 = i0 * EROWS + s0, r1 = i1 * EROWS + s1;
    g_tok_of_row[r0] = t; g_tok_of_row[r1] = t;
    g_tokrow[t * 2] = r0; g_tokrow[t * 2 + 1] = r1;
    g_tokgate[t * 2] = g0; g_tokgate[t * 2 + 1] = g1;
    #pragma unroll
    for (int e = 0; e < EE; e++) atomicAdd(&sP[e], p[e]);
    __syncthreads();
    if (tid < EE) atomicAdd(&g_Psum[tid], sP[tid]);
}

// ---------------- expert GEMM 1 (gathered A, GELU -> mid hi/lo) ----------------
__global__ void __launch_bounds__(256) egemm1_kernel(const float* __restrict__ eb1) {
    int e = blockIdx.z;
    int cnt = g_count[e];
    int row0 = blockIdx.y * 128;
    if (row0 >= cnt) return;
    int col0 = blockIdx.x * 128;
    extern __shared__ char smraw[];
    SmemGemm* S = (SmemGemm*)smraw;
    float (*Cs)[CPAD] = (float(*)[CPAD])smraw;
    __shared__ int s_tok[128];
    int tid = threadIdx.x;
    if (tid < 128) {
        int gr = row0 + tid;
        s_tok[tid] = (gr < cnt) ? g_tok_of_row[e * EROWS + gr] : -1;
    }
    __syncthreads();
    AccFrag acc[2][4];
    #pragma unroll
    for (int i = 0; i < 2; i++)
        #pragma unroll
        for (int j = 0; j < 4; j++) wmma::fill_fragment(acc[i][j], 0.0f);
    size_t woff = OFF_EW1 + (size_t)e * CC * FF;
    wmma_core(g_h_hi, g_h_lo, g_w_hi + woff, g_w_lo + woff, s_tok, 0, FF, CC, 0, col0, S, acc);
    stage_acc(acc, Cs, tid);
    #pragma unroll
    for (int u = 0; u < 16; u++) {
        int f = tid + u * 256;
        int r = f >> 5, c = (f & 31) * 4;
        if (row0 + r >= cnt) continue;
        int gc = col0 + c;
        float4 v = *(float4*)&Cs[r][c];
        float vv[4] = {v.x, v.y, v.z, v.w};
        __align__(8) __nv_bfloat16 hh[4], ll[4];
        #pragma unroll
        for (int j = 0; j < 4; j++) {
            float xx = vv[j] + eb1[e * FF + gc + j];
            float uu = 0.7978845608028654f * (xx + 0.044715f * xx * xx * xx);
            float ge = 0.5f * xx * (1.0f + tanhf(uu));
            split1(ge, hh[j], ll[j]);
        }
        size_t idx = ((size_t)e * EROWS + row0 + r) * FF + gc;
        *(uint2*)(g_mid_hi + idx) = *(uint2*)hh;
        *(uint2*)(g_mid_lo + idx) = *(uint2*)ll;
    }
}

// ---------------- expert GEMM 2 ----------------
__global__ void __launch_bounds__(256) egemm2_kernel(const float* __restrict__ eb2) {
    int e = blockIdx.z;
    int cnt = g_count[e];
    int row0 = blockIdx.y * 128;
    if (row0 >= cnt) return;
    int col0 = blockIdx.x * 128;
    extern __shared__ char smraw[];
    SmemGemm* S = (SmemGemm*)smraw;
    float (*Cs)[CPAD] = (float(*)[CPAD])smraw;
    int tid = threadIdx.x;
    AccFrag acc[2][4];
    #pragma unroll
    for (int i = 0; i < 2; i++)
        #pragma unroll
        for (int j = 0; j < 4; j++) wmma::fill_fragment(acc[i][j], 0.0f);
    size_t woff = OFF_EW2 + (size_t)e * FF * CC;
    wmma_core(g_mid_hi + (size_t)e * EROWS * FF, g_mid_lo + (size_t)e * EROWS * FF,
              g_w_hi + woff, g_w_lo + woff, nullptr, cnt, CC, FF, row0, col0, S, acc);
    stage_acc(acc, Cs, tid);
    #pragma unroll
    for (int u = 0; u < 16; u++) {
        int f = tid + u * 256;
        int r = f >> 5, c = (f & 31) * 4;
        if (row0 + r >= cnt) continue;
        int gc = col0 + c;
        float4 v = *(float4*)&Cs[r][c];
        v.x += eb2[e * CC + gc];     v.y += eb2[e * CC + gc + 1];
        v.z += eb2[e * CC + gc + 2]; v.w += eb2[e * CC + gc + 3];
        *(float4*)&g_eo[((size_t)e * EROWS + row0 + r) * CC + gc] = v;
    }
}

// ---------------- combine + aux ----------------
__global__ void combine_kernel(float* __restrict__ out) {
    int t = blockIdx.x;
    int tid = threadIdx.x;
    int r0 = g_tokrow[t * 2], r1 = g_tokrow[t * 2 + 1];
    float g0 = g_tokgate[t * 2], g1 = g_tokgate[t * 2 + 1];
    const float* x2 = g_x2 + (size_t)t * CC;
    const float* e0 = g_eo + (size_t)r0 * CC;
    const float* e1 = g_eo + (size_t)r1 * CC;
    float* orow = out + (size_t)t * CC;
    for (int c = tid; c < CC; c += 128)
        orow[c] = x2[c] + g0 * e0[c] + g1 * e1[c];
}

__global__ void aux_kernel(float* __restrict__ out, int out_size) {
    if (threadIdx.x == 0 && blockIdx.x == 0) {
        float a = 0.0f;
        for (int e = 0; e < EE; e++)
            a += (g_count[e] / (float)TOK) * (g_Psum[e] / (float)TOK);
        a *= (float)EE;
        if (out_size > TOK * CC) out[TOK * CC] = a;
    }
}

// ---------------- launch ----------------
extern "C" void kernel_launch(void* const* d_in, const int* in_sizes, int n_in,
                              void* d_out, int out_size) {
    const float* x      = (const float*)d_in[0];
    const float* vision = (const float*)d_in[1];
    const float* ln1_g = (const float*)d_in[2];  const float* ln1_b = (const float*)d_in[3];
    const float* ln2_g = (const float*)d_in[4];  const float* ln2_b = (const float*)d_in[5];
    const float* ln3_g = (const float*)d_in[6];  const float* ln3_b = (const float*)d_in[7];
    const float* sa_wq = (const float*)d_in[8];  const float* sa_bq = (const float*)d_in[9];
    const float* sa_wk = (const float*)d_in[10]; const float* sa_bk = (const float*)d_in[11];
    const float* sa_wv = (const float*)d_in[12]; const float* sa_bv = (const float*)d_in[13];
    const float* sa_wo = (const float*)d_in[14]; const float* sa_bo = (const float*)d_in[15];
    const float* ca_wq = (const float*)d_in[16]; const float* ca_bq = (const float*)d_in[17];
    const float* ca_wk = (const float*)d_in[18]; const float* ca_bk = (const float*)d_in[19];
    const float* ca_wv = (const float*)d_in[20]; const float* ca_bv = (const float*)d_in[21];
    const float* ca_wo = (const float*)d_in[22]; const float* ca_bo = (const float*)d_in[23];
    const float* rw    = (const float*)d_in[24]; const float* rb    = (const float*)d_in[25];
    const float* ew1   = (const float*)d_in[26]; const float* eb1   = (const float*)d_in[27];
    const float* ew2   = (const float*)d_in[28]; const float* eb2   = (const float*)d_in[29];
    float* out = (float*)d_out;

    float *p_h, *p_x1, *p_x2;
    __nv_bfloat16 *p_hh, *p_hl, *p_qh, *p_ql, *p_kh, *p_kl, *p_vh_, *p_vl_;
    __nv_bfloat16 *p_k2h, *p_k2l, *p_v2h, *p_v2l;
    __nv_bfloat16 *p_ath, *p_atl, *p_vih, *p_vil, *p_wh, *p_wl;
    cudaGetSymbolAddress((void**)&p_h,  g_h);
    cudaGetSymbolAddress((void**)&p_x1, g_x1);
    cudaGetSymbolAddress((void**)&p_x2, g_x2);
    cudaGetSymbolAddress((void**)&p_hh, g_h_hi);
    cudaGetSymbolAddress((void**)&p_hl, g_h_lo);
    cudaGetSymbolAddress((void**)&p_qh, g_q_hi);
    cudaGetSymbolAddress((void**)&p_ql, g_q_lo);
    cudaGetSymbolAddress((void**)&p_kh, g_k_hi);
    cudaGetSymbolAddress((void**)&p_kl, g_k_lo);
    cudaGetSymbolAddress((void**)&p_vh_, g_v_hi);
    cudaGetSymbolAddress((void**)&p_vl_, g_v_lo);
    cudaGetSymbolAddress((void**)&p_k2h, g_k2_hi);
    cudaGetSymbolAddress((void**)&p_k2l, g_k2_lo);
    cudaGetSymbolAddress((void**)&p_v2h, g_v2_hi);
    cudaGetSymbolAddress((void**)&p_v2l, g_v2_lo);
    cudaGetSymbolAddress((void**)&p_ath, g_att_hi);
    cudaGetSymbolAddress((void**)&p_atl, g_att_lo);
    cudaGetSymbolAddress((void**)&p_vih, g_vis_hi);
    cudaGetSymbolAddress((void**)&p_vil, g_vis_lo);
    cudaGetSymbolAddress((void**)&p_wh, g_w_hi);
    cudaGetSymbolAddress((void**)&p_wl, g_w_lo);

    const int gemm_smem = GEMM_SMEM_BYTES;
    cudaFuncSetAttribute(gemm128,       cudaFuncAttributeMaxDynamicSharedMemorySize, gemm_smem);
    cudaFuncSetAttribute(kvgemm128,     cudaFuncAttributeMaxDynamicSharedMemorySize, gemm_smem);
    cudaFuncSetAttribute(egemm1_kernel, cudaFuncAttributeMaxDynamicSharedMemorySize, gemm_smem);
    cudaFuncSetAttribute(egemm2_kernel, cudaFuncAttributeMaxDynamicSharedMemorySize, gemm_smem);

    // lazily-created side streams + events (host objects only; identical work graph every call)
    static cudaStream_t s1 = nullptr, s2 = nullptr;
    static cudaEvent_t evF = nullptr, evB = nullptr, evKV = nullptr, evLn1 = nullptr;
    if (!s1) {
        cudaStreamCreateWithFlags(&s1, cudaStreamNonBlocking);
        cudaStreamCreateWithFlags(&s2, cudaStreamNonBlocking);
        cudaEventCreateWithFlags(&evF,   cudaEventDisableTiming);
        cudaEventCreateWithFlags(&evB,   cudaEventDisableTiming);
        cudaEventCreateWithFlags(&evKV,  cudaEventDisableTiming);
        cudaEventCreateWithFlags(&evLn1, cudaEventDisableTiming);
    }

    dim3 gC(CC / 128, TOK / 128);
    dim3 gKVsa(2, TOK / 128);
    dim3 gKVca(2, (BB * MV) / 128);
    dim3 gAtt(NN / 128, HH, BB);

    auto conv = [&](const float* src, size_t off, int n, cudaStream_t st) {
        conv_kernel<<<(n / 4 + 255) / 256, 256, 0, st>>>(src, p_wh + off, p_wl + off, n);
    };

    // ---- fork s1: everything independent of block 1 ----
    cudaEventRecord(evF, 0);
    cudaStreamWaitEvent(s1, evF, 0);
    conv(ca_wq, OFF_CAWQ, SZ_QO, s1); conv(ca_wk, OFF_CAWK, SZ_KV, s1);
    conv(ca_wv, OFF_CAWV, SZ_KV, s1); conv(ca_wo, OFF_CAWO, SZ_QO, s1);
    conv_kernel<<<(BB * MV * CC / 4 + 255) / 256, 256, 0, s1>>>(vision, p_vih, p_vil, BB * MV * CC);
    conv(ew1, OFF_EW1, EE * CC * FF, s1);
    conv(ew2, OFF_EW2, EE * FF * CC, s1);
    kvgemm128<<<gKVca, 256, gemm_smem, s1>>>(p_vih, p_vil, OFF_CAWK, ca_bk, OFF_CAWV, ca_bv,
                                             p_k2h, p_k2l, p_v2h, p_v2l, BB * MV, CC);
    cudaEventRecord(evB, s1);

    // ---- main stream: SA weight conv + block 1 ----
    conv(sa_wq, OFF_SAWQ, SZ_QO, 0); conv(sa_wk, OFF_SAWK, SZ_KV, 0);
    conv(sa_wv, OFF_SAWV, SZ_KV, 0); conv(sa_wo, OFF_SAWO, SZ_QO, 0);
    ln_kernel<<<TOK, 256>>>(x, ln1_g, ln1_b, p_h, p_hh, p_hl);
    cudaEventRecord(evLn1, 0);
    cudaStreamWaitEvent(s2, evLn1, 0);
    kvgemm128<<<gKVsa, 256, gemm_smem, s2>>>(p_hh, p_hl, OFF_SAWK, sa_bk, OFF_SAWV, sa_bv,
                                             p_kh, p_kl, p_vh_, p_vl_, TOK, CC);
    cudaEventRecord(evKV, s2);
    gemm128<<<gC, 256, gemm_smem>>>(p_hh, p_hl, OFF_SAWQ, sa_bq, nullptr,
                                    nullptr, p_qh, p_ql, TOK, CC, CC);
    cudaStreamWaitEvent(0, evKV, 0);
    flash_mma<<<gAtt, 256>>>(p_qh, p_ql, p_kh, p_kl, p_vh_, p_vl_, p_ath, p_atl, NN, 1);
    gemm128<<<gC, 256, gemm_smem>>>(p_ath, p_atl, OFF_SAWO, sa_bo, x,
                                    p_x1, nullptr, nullptr, TOK, CC, CC);

    // ---- block 2: CA (join s1 before first consumer of its outputs) ----
    ln_kernel<<<TOK, 256>>>(p_x1, ln2_g, ln2_b, p_h, p_hh, p_hl);
    cudaStreamWaitEvent(0, evB, 0);
    gemm128<<<gC, 256, gemm_smem>>>(p_hh, p_hl, OFF_CAWQ, ca_bq, nullptr,
                                    nullptr, p_qh, p_ql, TOK, CC, CC);
    flash_mma<<<gAtt, 256>>>(p_qh, p_ql, p_k2h, p_k2l, p_v2h, p_v2l, p_ath, p_atl, MV, 0);
    gemm128<<<gC, 256, gemm_smem>>>(p_ath, p_atl, OFF_CAWO, ca_bo, p_x1,
                                    p_x2, nullptr, nullptr, TOK, CC, CC);

    // ---- block 3: MoE ----
    ln_kernel<<<TOK, 256>>>(p_x2, ln3_g, ln3_b, p_h, p_hh, p_hl);
    zero_kernel<<<1, 32>>>();
    router_kernel<<<TOK / 256, 256>>>(rw, rb);
    egemm1_kernel<<<dim3(FF / 128, EROWS / 128, EE), 256, gemm_smem>>>(eb1);
    egemm2_kernel<<<dim3(CC / 128, EROWS / 128, EE), 256, gemm_smem>>>(eb2);
    combine_kernel<<<TOK, 128>>>(out);
    aux_kernel<<<1, 1>>>(out, out_size);
}

// round 14
// speedup vs baseline: 1.0325x; 1.0109x over previous
#include <cuda_runtime.h>
#include <cuda_bf16.h>
#include <mma.h>
#include <math.h>
#include <cstdint>

using namespace nvcuda;

// ---------------- problem constants ----------------
#define BB 4
#define NN 2048
#define MV 576
#define CC 512
#define HH 8
#define KVH 2
#define DD 64
#define EE 8
#define TOPK 2
#define FF 2048
#define TOK (BB*NN)
#define KVDIM (KVH*DD)       // 128
#define EROWS 8192

// weight buffer offsets (elements)
#define SZ_QO (CC*CC)
#define SZ_KV (CC*KVDIM)
#define OFF_SAWQ 0
#define OFF_SAWK (OFF_SAWQ+SZ_QO)
#define OFF_SAWV (OFF_SAWK+SZ_KV)
#define OFF_SAWO (OFF_SAWV+SZ_KV)
#define OFF_CAWQ (OFF_SAWO+SZ_QO)
#define OFF_CAWK (OFF_CAWQ+SZ_QO)
#define OFF_CAWV (OFF_CAWK+SZ_KV)
#define OFF_CAWO (OFF_CAWV+SZ_KV)
#define OFF_EW1  (OFF_CAWO+SZ_QO)
#define OFF_EW2  (OFF_EW1 + (size_t)EE*CC*FF)
#define WTOT     (OFF_EW2 + (size_t)EE*FF*CC)

// ---------------- static scratch ----------------
__device__ float g_h  [(size_t)TOK*CC];     // fp32 LN out (router)
__device__ float g_x1 [(size_t)TOK*CC];
__device__ float g_x2 [(size_t)TOK*CC];
__device__ float g_eo [(size_t)EE*EROWS*CC];
__device__ __nv_bfloat16 g_h_hi [(size_t)TOK*CC];
__device__ __nv_bfloat16 g_h_lo [(size_t)TOK*CC];
__device__ __nv_bfloat16 g_q_hi [(size_t)TOK*CC];
__device__ __nv_bfloat16 g_q_lo [(size_t)TOK*CC];
__device__ __nv_bfloat16 g_k_hi [(size_t)TOK*KVDIM];
__device__ __nv_bfloat16 g_k_lo [(size_t)TOK*KVDIM];
__device__ __nv_bfloat16 g_v_hi [(size_t)TOK*KVDIM];
__device__ __nv_bfloat16 g_v_lo [(size_t)TOK*KVDIM];
// dedicated CA K/V (produced early on side stream; must not alias SA K/V)
__device__ __nv_bfloat16 g_k2_hi[(size_t)BB*MV*KVDIM];
__device__ __nv_bfloat16 g_k2_lo[(size_t)BB*MV*KVDIM];
__device__ __nv_bfloat16 g_v2_hi[(size_t)BB*MV*KVDIM];
__device__ __nv_bfloat16 g_v2_lo[(size_t)BB*MV*KVDIM];
__device__ __nv_bfloat16 g_att_hi[(size_t)TOK*CC];
__device__ __nv_bfloat16 g_att_lo[(size_t)TOK*CC];
__device__ __nv_bfloat16 g_vis_hi[(size_t)BB*MV*CC];
__device__ __nv_bfloat16 g_vis_lo[(size_t)BB*MV*CC];
__device__ __nv_bfloat16 g_mid_hi[(size_t)EE*EROWS*FF];
__device__ __nv_bfloat16 g_mid_lo[(size_t)EE*EROWS*FF];
__device__ __nv_bfloat16 g_w_hi[WTOT];
__device__ __nv_bfloat16 g_w_lo[WTOT];
__device__ int   g_count[EE];
__device__ float g_Psum[EE];
__device__ int   g_tokrow [TOK*TOPK];
__device__ float g_tokgate[TOK*TOPK];
__device__ int   g_tok_of_row[EE*EROWS];

// ---------------- helpers ----------------
__device__ __forceinline__ void split1(float v, __nv_bfloat16& h, __nv_bfloat16& l) {
    h = __float2bfloat16(v);
    l = __float2bfloat16(v - __bfloat162float(h));
}
__device__ __forceinline__ unsigned pk2(float lo, float hi) {
    unsigned r;
    asm("cvt.rn.bf16x2.f32 %0, %1, %2;" : "=r"(r) : "f"(hi), "f"(lo));
    return r;
}
__device__ __forceinline__ float bfrt(float x) {
    return __bfloat162float(__float2bfloat16(x));
}
__device__ __forceinline__ void mma16816(float* c, const unsigned* a, const unsigned* b) {
    asm volatile(
        "mma.sync.aligned.m16n8k16.row.col.f32.bf16.bf16.f32 "
        "{%0,%1,%2,%3},{%4,%5,%6,%7},{%8,%9},{%0,%1,%2,%3};"
        : "+f"(c[0]), "+f"(c[1]), "+f"(c[2]), "+f"(c[3])
        : "r"(a[0]), "r"(a[1]), "r"(a[2]), "r"(a[3]), "r"(b[0]), "r"(b[1]));
}
// 16B async copy; zero-fill when !valid
__device__ __forceinline__ void cp16(void* dst, const void* src, bool valid) {
    unsigned d = (unsigned)__cvta_generic_to_shared(dst);
    int sz = valid ? 16 : 0;
    asm volatile("cp.async.cg.shared.global [%0], [%1], 16, %2;\n" :: "r"(d), "l"(src), "r"(sz));
}
#define CP_COMMIT asm volatile("cp.async.commit_group;\n" ::: "memory")
#define CP_WAIT0  asm volatile("cp.async.wait_group 0;\n" ::: "memory")
#define CP_WAIT1  asm volatile("cp.async.wait_group 1;\n" ::: "memory")

// ---------------- fp32 -> hi/lo bf16 conversion ----------------
__global__ void conv_kernel(const float* __restrict__ src, __nv_bfloat16* __restrict__ hi,
                            __nv_bfloat16* __restrict__ lo, int n) {
    int i = (blockIdx.x * blockDim.x + threadIdx.x) * 4;
    if (i >= n) return;
    float4 v = *(const float4*)(src + i);
    __align__(8) __nv_bfloat16 h[4], l[4];
    split1(v.x, h[0], l[0]); split1(v.y, h[1], l[1]);
    split1(v.z, h[2], l[2]); split1(v.w, h[3], l[3]);
    *(uint2*)(hi + i) = *(uint2*)h;
    *(uint2*)(lo + i) = *(uint2*)l;
}

// ---------------- LayerNorm (fp32 + hi/lo bf16 out) ----------------
__global__ void ln_kernel(const float* __restrict__ x, const float* __restrict__ g,
                          const float* __restrict__ b, float* __restrict__ o,
                          __nv_bfloat16* __restrict__ ohi, __nv_bfloat16* __restrict__ olo) {
    int t = blockIdx.x;
    int tid = threadIdx.x;
    const float* xr = x + (size_t)t * CC;
    float v0 = xr[tid], v1 = xr[tid + 256];
    __shared__ float red[256];
    red[tid] = v0 + v1; __syncthreads();
    for (int off = 128; off > 0; off >>= 1) {
        if (tid < off) red[tid] += red[tid + off];
        __syncthreads();
    }
    float mu = red[0] * (1.0f / CC);
    __syncthreads();
    float d0 = v0 - mu, d1 = v1 - mu;
    red[tid] = d0 * d0 + d1 * d1; __syncthreads();
    for (int off = 128; off > 0; off >>= 1) {
        if (tid < off) red[tid] += red[tid + off];
        __syncthreads();
    }
    float rstd = rsqrtf(red[0] * (1.0f / CC) + 1e-6f);
    size_t base = (size_t)t * CC;
    float r0 = d0 * rstd * g[tid]       + b[tid];
    float r1 = d1 * rstd * g[tid + 256] + b[tid + 256];
    if (o) { o[base + tid] = r0; o[base + tid + 256] = r1; }
    __nv_bfloat16 h, l;
    split1(r0, h, l); ohi[base + tid] = h;       olo[base + tid] = l;
    split1(r1, h, l); ohi[base + tid + 256] = h; olo[base + tid + 256] = l;
}

// ---------------- wmma split-bf16 GEMM core, 3-stage cp.async pipeline ----------------
// One barrier per 32-K chunk: [wait<=1; barrier; issue(c+2); mma(c)].
#define APAD 40
#define BPAD 136
#define CPAD 132
struct SmemGemm {
    __nv_bfloat16 Ah[3][128][APAD];
    __nv_bfloat16 Al[3][128][APAD];
    __nv_bfloat16 Bh[3][32][BPAD];
    __nv_bfloat16 Bl[3][32][BPAD];
};
#define GEMM_SMEM_BYTES 113664   // sizeof(SmemGemm); Cs staging (67,584) aliases

typedef wmma::fragment<wmma::accumulator, 16, 16, 16, float> AccFrag;

__device__ __forceinline__ void wmma_core(
        const __nv_bfloat16* __restrict__ Ahg, const __nv_bfloat16* __restrict__ Alg,
        const __nv_bfloat16* __restrict__ Bhg, const __nv_bfloat16* __restrict__ Blg,
        const int* __restrict__ tokidx,
        int Mr, int Nc, int Kd, int row0, int col0,
        SmemGemm* S, AccFrag (&acc)[2][4]) {
    int tid = threadIdx.x;
    int w = tid >> 5, wm = w & 3, wn = w >> 2;
    int ra = tid >> 1, kc = (tid & 1) * 16;
    int rb = tid >> 3, cb = (tid & 7) * 16;

    size_t arow; bool avalid;
    if (tokidx) {
        int tok = tokidx[ra];
        avalid = (tok >= 0);
        arow = (size_t)(avalid ? tok : 0) * Kd;
    } else {
        int gr = row0 + ra;
        avalid = (gr < Mr);
        arow = (size_t)(avalid ? gr : 0) * Kd;
    }

    int nch = Kd / 32;
    auto issue = [&](int c, int buf) {
        int k0 = c * 32;
        size_t ab = arow + k0 + kc;
        cp16(&S->Ah[buf][ra][kc],     Ahg + ab,     avalid);
        cp16(&S->Ah[buf][ra][kc + 8], Ahg + ab + 8, avalid);
        cp16(&S->Al[buf][ra][kc],     Alg + ab,     avalid);
        cp16(&S->Al[buf][ra][kc + 8], Alg + ab + 8, avalid);
        size_t bb = (size_t)(k0 + rb) * Nc + col0 + cb;
        cp16(&S->Bh[buf][rb][cb],     Bhg + bb,     true);
        cp16(&S->Bh[buf][rb][cb + 8], Bhg + bb + 8, true);
        cp16(&S->Bl[buf][rb][cb],     Blg + bb,     true);
        cp16(&S->Bl[buf][rb][cb + 8], Blg + bb + 8, true);
        CP_COMMIT;
    };

    // prologue: prefetch chunks 0 and 1 (nch >= 4 always here)
    issue(0, 0);
    issue(1, 1);
    int buf = 0, nbuf = 2;   // buf of chunk c; nbuf = buffer for chunk c+2
    #pragma unroll 1
    for (int c = 0; c < nch; c++) {
        CP_WAIT1;            // chunk c resident
        __syncthreads();     // publish buf c; all warps past mma(c-1) -> safe to refill nbuf
        if (c + 2 < nch) issue(c + 2, nbuf);
        #pragma unroll
        for (int ks = 0; ks < 2; ks++) {
            wmma::fragment<wmma::matrix_a, 16,16,16, __nv_bfloat16, wmma::row_major> ah[2], al[2];
            wmma::fragment<wmma::matrix_b, 16,16,16, __nv_bfloat16, wmma::row_major> bh[4], bl[4];
            #pragma unroll
            for (int i = 0; i < 2; i++) {
                wmma::load_matrix_sync(ah[i], &S->Ah[buf][wm*32 + i*16][ks*16], APAD);
                wmma::load_matrix_sync(al[i], &S->Al[buf][wm*32 + i*16][ks*16], APAD);
            }
            #pragma unroll
            for (int j = 0; j < 4; j++) {
                wmma::load_matrix_sync(bh[j], &S->Bh[buf][ks*16][wn*64 + j*16], BPAD);
                wmma::load_matrix_sync(bl[j], &S->Bl[buf][ks*16][wn*64 + j*16], BPAD);
            }
            #pragma unroll
            for (int i = 0; i < 2; i++)
                #pragma unroll
                for (int j = 0; j < 4; j++) {
                    wmma::mma_sync(acc[i][j], ah[i], bh[j], acc[i][j]);
                    wmma::mma_sync(acc[i][j], ah[i], bl[j], acc[i][j]);
                    wmma::mma_sync(acc[i][j], al[i], bh[j], acc[i][j]);
                }
        }
        buf = (buf == 2) ? 0 : buf + 1;
        nbuf = (nbuf == 2) ? 0 : nbuf + 1;
    }
    __syncthreads();  // all warps done with smem stages before Cs aliasing
}

__device__ __forceinline__ void stage_acc(AccFrag (&acc)[2][4], float (*Cs)[CPAD], int tid) {
    int w = tid >> 5, wm = w & 3, wn = w >> 2;
    #pragma unroll
    for (int i = 0; i < 2; i++)
        #pragma unroll
        for (int j = 0; j < 4; j++)
            wmma::store_matrix_sync(&Cs[wm*32 + i*16][wn*64 + j*16], acc[i][j],
                                    CPAD, wmma::mem_row_major);
    __syncthreads();
}

// ---------------- generic GEMM: fp32 out (bias/resid) OR hi/lo bf16 out ----------------
__global__ void __launch_bounds__(256) gemm128(
        const __nv_bfloat16* __restrict__ Ahg, const __nv_bfloat16* __restrict__ Alg,
        int woff, const float* __restrict__ bias, const float* __restrict__ resid,
        float* __restrict__ out,
        __nv_bfloat16* __restrict__ ohi, __nv_bfloat16* __restrict__ olo,
        int Mr, int Nc, int Kd) {
    extern __shared__ char smraw[];
    SmemGemm* S = (SmemGemm*)smraw;
    float (*Cs)[CPAD] = (float(*)[CPAD])smraw;
    int tid = threadIdx.x;
    int row0 = blockIdx.y * 128, col0 = blockIdx.x * 128;
    AccFrag acc[2][4];
    #pragma unroll
    for (int i = 0; i < 2; i++)
        #pragma unroll
        for (int j = 0; j < 4; j++) wmma::fill_fragment(acc[i][j], 0.0f);
    wmma_core(Ahg, Alg, g_w_hi + woff, g_w_lo + woff, nullptr, Mr, Nc, Kd, row0, col0, S, acc);
    stage_acc(acc, Cs, tid);
    #pragma unroll
    for (int u = 0; u < 16; u++) {
        int f = tid + u * 256;
        int r = f >> 5, c = (f & 31) * 4;
        int gr = row0 + r;
        if (gr >= Mr) continue;
        int gc = col0 + c;
        float4 v = *(float4*)&Cs[r][c];
        if (bias) { v.x += bias[gc]; v.y += bias[gc+1]; v.z += bias[gc+2]; v.w += bias[gc+3]; }
        if (resid) {
            float4 rr = *(const float4*)(resid + (size_t)gr * Nc + gc);
            v.x += rr.x; v.y += rr.y; v.z += rr.z; v.w += rr.w;
        }
        if (out) {
            *(float4*)(out + (size_t)gr * Nc + gc) = v;
        } else {
            __align__(8) __nv_bfloat16 hh[4], ll[4];
            split1(v.x, hh[0], ll[0]); split1(v.y, hh[1], ll[1]);
            split1(v.z, hh[2], ll[2]); split1(v.w, hh[3], ll[3]);
            *(uint2*)(ohi + (size_t)gr * Nc + gc) = *(uint2*)hh;
            *(uint2*)(olo + (size_t)gr * Nc + gc) = *(uint2*)ll;
        }
    }
}

// ---------------- fused K+V projection -> hi/lo bf16 ----------------
__global__ void __launch_bounds__(256) kvgemm128(
        const __nv_bfloat16* __restrict__ Ahg, const __nv_bfloat16* __restrict__ Alg,
        int woffk, const float* __restrict__ bk,
        int woffv, const float* __restrict__ bv,
        __nv_bfloat16* __restrict__ okh, __nv_bfloat16* __restrict__ okl,
        __nv_bfloat16* __restrict__ ovh, __nv_bfloat16* __restrict__ ovl,
        int Mr, int Kd) {
    extern __shared__ char smraw[];
    SmemGemm* S = (SmemGemm*)smraw;
    float (*Cs)[CPAD] = (float(*)[CPAD])smraw;
    int woff          = (blockIdx.x == 0) ? woffk : woffv;
    const float* bias = (blockIdx.x == 0) ? bk : bv;
    __nv_bfloat16* oh = (blockIdx.x == 0) ? okh : ovh;
    __nv_bfloat16* ol = (blockIdx.x == 0) ? okl : ovl;
    int tid = threadIdx.x;
    int row0 = blockIdx.y * 128;
    AccFrag acc[2][4];
    #pragma unroll
    for (int i = 0; i < 2; i++)
        #pragma unroll
        for (int j = 0; j < 4; j++) wmma::fill_fragment(acc[i][j], 0.0f);
    wmma_core(Ahg, Alg, g_w_hi + woff, g_w_lo + woff, nullptr, Mr, KVDIM, Kd, row0, 0, S, acc);
    stage_acc(acc, Cs, tid);
    #pragma unroll
    for (int u = 0; u < 16; u++) {
        int f = tid + u * 256;
        int r = f >> 5, c = (f & 31) * 4;
        int gr = row0 + r;
        if (gr >= Mr) continue;
        float4 v = *(float4*)&Cs[r][c];
        v.x += bias[c]; v.y += bias[c+1]; v.z += bias[c+2]; v.w += bias[c+3];
        __align__(8) __nv_bfloat16 hh[4], ll[4];
        split1(v.x, hh[0], ll[0]); split1(v.y, hh[1], ll[1]);
        split1(v.z, hh[2], ll[2]); split1(v.w, hh[3], ll[3]);
        *(uint2*)(oh + (size_t)gr * KVDIM + c) = *(uint2*)hh;
        *(uint2*)(ol + (size_t)gr * KVDIM + c) = *(uint2*)ll;
    }
}

// ---------------- FA2 flash attention: mma.m16n8k16 split-bf16 ----------------
#define KPAD 72
__global__ void __launch_bounds__(256) flash_mma(
        const __nv_bfloat16* __restrict__ qhi, const __nv_bfloat16* __restrict__ qlo,
        const __nv_bfloat16* __restrict__ khi, const __nv_bfloat16* __restrict__ klo,
        const __nv_bfloat16* __restrict__ vhi, const __nv_bfloat16* __restrict__ vlo,
        __nv_bfloat16* __restrict__ ohi, __nv_bfloat16* __restrict__ olo,
        int n_kv, int causal) {
    __shared__ __nv_bfloat16 Kh[64][KPAD], Kl[64][KPAD], Vth[64][KPAD], Vtl[64][KPAD];
    int qt = blockIdx.x, h = blockIdx.y, b = blockIdx.z;
    int g = h >> 2;
    int tid = threadIdx.x, w = tid >> 5, lane = tid & 31;
    int r0 = lane >> 2, tq = lane & 3;
    int qrow = qt * 128 + w * 16 + r0;

    unsigned qah[4][4], qal[4][4];
    {
        const __nv_bfloat16* q0h = qhi + ((size_t)(b * NN + qrow)) * CC + h * DD;
        const __nv_bfloat16* q1h = qhi + ((size_t)(b * NN + qrow + 8)) * CC + h * DD;
        const __nv_bfloat16* q0l = qlo + ((size_t)(b * NN + qrow)) * CC + h * DD;
        const __nv_bfloat16* q1l = qlo + ((size_t)(b * NN + qrow + 8)) * CC + h * DD;
        #pragma unroll
        for (int ks = 0; ks < 4; ks++) {
            int c = ks * 16 + tq * 2;
            qah[ks][0] = *(const unsigned*)(q0h + c);
            qah[ks][1] = *(const unsigned*)(q1h + c);
            qah[ks][2] = *(const unsigned*)(q0h + c + 8);
            qah[ks][3] = *(const unsigned*)(q1h + c + 8);
            qal[ks][0] = *(const unsigned*)(q0l + c);
            qal[ks][1] = *(const unsigned*)(q1l + c);
            qal[ks][2] = *(const unsigned*)(q0l + c + 8);
            qal[ks][3] = *(const unsigned*)(q1l + c + 8);
        }
    }

    float m0 = -1e30f, m1 = -1e30f, l0 = 0.0f, l1 = 0.0f;
    float o[8][4] = {};

    int key_l = tid >> 2, dseg = (tid & 3) * 16;
    int nkt = causal ? (2 * qt + 2) : (n_kv / 64);
    for (int kt = 0; kt < nkt; kt++) {
        __syncthreads();
        {
            size_t base = ((size_t)(b * n_kv + kt * 64 + key_l)) * KVDIM + g * DD + dseg;
            *(uint4*)&Kh[key_l][dseg]     = *(const uint4*)(khi + base);
            *(uint4*)&Kh[key_l][dseg + 8] = *(const uint4*)(khi + base + 8);
            *(uint4*)&Kl[key_l][dseg]     = *(const uint4*)(klo + base);
            *(uint4*)&Kl[key_l][dseg + 8] = *(const uint4*)(klo + base + 8);
            const __nv_bfloat16* vh = vhi + base;
            const __nv_bfloat16* vl = vlo + base;
            #pragma unroll
            for (int i = 0; i < 16; i++) {
                Vth[dseg + i][key_l] = vh[i];
                Vtl[dseg + i][key_l] = vl[i];
            }
        }
        __syncthreads();

        float sc[8][4] = {};
        #pragma unroll
        for (int nt = 0; nt < 8; nt++) {
            int krow = nt * 8 + r0;
            #pragma unroll
            for (int ks = 0; ks < 4; ks++) {
                int c = ks * 16 + tq * 2;
                unsigned bh[2], bl[2];
                bh[0] = *(const unsigned*)&Kh[krow][c];
                bh[1] = *(const unsigned*)&Kh[krow][c + 8];
                bl[0] = *(const unsigned*)&Kl[krow][c];
                bl[1] = *(const unsigned*)&Kl[krow][c + 8];
                mma16816(sc[nt], qah[ks], bh);
                mma16816(sc[nt], qah[ks], bl);
                mma16816(sc[nt], qal[ks], bh);
            }
        }
        bool maskit = causal && (kt >= 2 * qt);
        #pragma unroll
        for (int nt = 0; nt < 8; nt++) {
            #pragma unroll
            for (int j = 0; j < 4; j++) {
                float v = sc[nt][j] * 0.125f;
                if (maskit) {
                    int col = kt * 64 + nt * 8 + tq * 2 + (j & 1);
                    int row = qt * 128 + w * 16 + r0 + ((j >> 1) ? 8 : 0);
                    if (col > row) v = -1e9f;
                }
                sc[nt][j] = v;
            }
        }
        float rm0 = -1e30f, rm1 = -1e30f;
        #pragma unroll
        for (int nt = 0; nt < 8; nt++) {
            rm0 = fmaxf(rm0, fmaxf(sc[nt][0], sc[nt][1]));
            rm1 = fmaxf(rm1, fmaxf(sc[nt][2], sc[nt][3]));
        }
        #pragma unroll
        for (int off = 1; off < 4; off <<= 1) {
            rm0 = fmaxf(rm0, __shfl_xor_sync(0xffffffffu, rm0, off));
            rm1 = fmaxf(rm1, __shfl_xor_sync(0xffffffffu, rm1, off));
        }
        float mn0 = fmaxf(m0, rm0), mn1 = fmaxf(m1, rm1);
        float al0 = __expf(m0 - mn0), al1 = __expf(m1 - mn1);
        m0 = mn0; m1 = mn1;
        float rs0 = 0.0f, rs1 = 0.0f;
        #pragma unroll
        for (int nt = 0; nt < 8; nt++) {
            sc[nt][0] = __expf(sc[nt][0] - mn0);
            sc[nt][1] = __expf(sc[nt][1] - mn0);
            sc[nt][2] = __expf(sc[nt][2] - mn1);
            sc[nt][3] = __expf(sc[nt][3] - mn1);
            rs0 += sc[nt][0] + sc[nt][1];
            rs1 += sc[nt][2] + sc[nt][3];
        }
        #pragma unroll
        for (int off = 1; off < 4; off <<= 1) {
            rs0 += __shfl_xor_sync(0xffffffffu, rs0, off);
            rs1 += __shfl_xor_sync(0xffffffffu, rs1, off);
        }
        l0 = l0 * al0 + rs0;
        l1 = l1 * al1 + rs1;
        #pragma unroll
        for (int nt = 0; nt < 8; nt++) {
            o[nt][0] *= al0; o[nt][1] *= al0;
            o[nt][2] *= al1; o[nt][3] *= al1;
        }
        #pragma unroll
        for (int kp = 0; kp < 4; kp++) {
            unsigned pah[4], pal[4];
            {
                float x0 = sc[2*kp][0],   x1 = sc[2*kp][1];
                float x2 = sc[2*kp][2],   x3 = sc[2*kp][3];
                float y0 = sc[2*kp+1][0], y1 = sc[2*kp+1][1];
                float y2 = sc[2*kp+1][2], y3 = sc[2*kp+1][3];
                pah[0] = pk2(x0, x1); pah[1] = pk2(x2, x3);
                pah[2] = pk2(y0, y1); pah[3] = pk2(y2, y3);
                pal[0] = pk2(x0 - bfrt(x0), x1 - bfrt(x1));
                pal[1] = pk2(x2 - bfrt(x2), x3 - bfrt(x3));
                pal[2] = pk2(y0 - bfrt(y0), y1 - bfrt(y1));
                pal[3] = pk2(y2 - bfrt(y2), y3 - bfrt(y3));
            }
            #pragma unroll
            for (int nt = 0; nt < 8; nt++) {
                int drow = nt * 8 + r0;
                int c = kp * 16 + tq * 2;
                unsigned bh[2], bl[2];
                bh[0] = *(const unsigned*)&Vth[drow][c];
                bh[1] = *(const unsigned*)&Vth[drow][c + 8];
                bl[0] = *(const unsigned*)&Vtl[drow][c];
                bl[1] = *(const unsigned*)&Vtl[drow][c + 8];
                mma16816(o[nt], pah, bh);
                mma16816(o[nt], pah, bl);
                mma16816(o[nt], pal, bh);
            }
        }
    }
    float inv0 = 1.0f / l0, inv1 = 1.0f / l1;
    size_t base0 = ((size_t)(b * NN + qrow)) * CC + h * DD;
    size_t base1 = ((size_t)(b * NN + qrow + 8)) * CC + h * DD;
    #pragma unroll
    for (int nt = 0; nt < 8; nt++) {
        int d = nt * 8 + tq * 2;
        float v0 = o[nt][0] * inv0, v1 = o[nt][1] * inv0;
        float v2 = o[nt][2] * inv1, v3 = o[nt][3] * inv1;
        *(unsigned*)(ohi + base0 + d) = pk2(bfrt(v0), bfrt(v1));
        *(unsigned*)(olo + base0 + d) = pk2(v0 - bfrt(v0), v1 - bfrt(v1));
        *(unsigned*)(ohi + base1 + d) = pk2(bfrt(v2), bfrt(v3));
        *(unsigned*)(olo + base1 + d) = pk2(v2 - bfrt(v2), v3 - bfrt(v3));
    }
}

// ---------------- MoE routing ----------------
__global__ void zero_kernel() {
    int t = threadIdx.x;
    if (t < EE) { g_count[t] = 0; g_Psum[t] = 0.0f; }
}

__global__ void router_kernel(const float* __restrict__ rw, const float* __restrict__ rb) {
    __shared__ float sP[EE];
    int tid = threadIdx.x;
    if (tid < EE) sP[tid] = 0.0f;
    __syncthreads();
    int t = blockIdx.x * blockDim.x + tid;
    float logit[EE];
    const float* hrow = g_h + (size_t)t * CC;
    #pragma unroll
    for (int e = 0; e < EE; e++) logit[e] = rb[e];
    for (int k = 0; k < CC; k++) {
        float hv = hrow[k];
        const float* wr = rw + k * EE;
        #pragma unroll
        for (int e = 0; e < EE; e++) logit[e] += hv * wr[e];
    }
    float mx = logit[0];
    #pragma unroll
    for (int e = 1; e < EE; e++) mx = fmaxf(mx, logit[e]);
    float p[EE], ps = 0.0f;
    #pragma unroll
    for (int e = 0; e < EE; e++) { p[e] = __expf(logit[e] - mx); ps += p[e]; }
    float invs = 1.0f / ps;
    #pragma unroll
    for (int e = 0; e < EE; e++) p[e] *= invs;
    int i0 = 0;
    #pragma unroll
    for (int e = 1; e < EE; e++) if (p[e] > p[i0]) i0 = e;
    int i1 = (i0 == 0) ? 1 : 0;
    #pragma unroll
    for (int e = 0; e < EE; e++) if (e != i0 && p[e] > p[i1]) i1 = e;
    float gs = p[i0] + p[i1];
    float g0 = p[i0] / gs, g1 = p[i1] / gs;
    int s0 = atomicAdd(&g_count[i0], 1);
    int s1 = atomicAdd(&g_count[i1], 1);
    int r0 = i0 * EROWS + s0, r1 = i1 * EROWS + s1;
    g_tok_of_row[r0] = t; g_tok_of_row[r1] = t;
    g_tokrow[t * 2] = r0; g_tokrow[t * 2 + 1] = r1;
    g_tokgate[t * 2] = g0; g_tokgate[t * 2 + 1] = g1;
    #pragma unroll
    for (int e = 0; e < EE; e++) atomicAdd(&sP[e], p[e]);
    __syncthreads();
    if (tid < EE) atomicAdd(&g_Psum[tid], sP[tid]);
}

// ---------------- expert GEMM 1 (gathered A, GELU -> mid hi/lo) ----------------
__global__ void __launch_bounds__(256) egemm1_kernel(const float* __restrict__ eb1) {
    int e = blockIdx.z;
    int cnt = g_count[e];
    int row0 = blockIdx.y * 128;
    if (row0 >= cnt) return;
    int col0 = blockIdx.x * 128;
    extern __shared__ char smraw[];
    SmemGemm* S = (SmemGemm*)smraw;
    float (*Cs)[CPAD] = (float(*)[CPAD])smraw;
    __shared__ int s_tok[128];
    int tid = threadIdx.x;
    if (tid < 128) {
        int gr = row0 + tid;
        s_tok[tid] = (gr < cnt) ? g_tok_of_row[e * EROWS + gr] : -1;
    }
    __syncthreads();
    AccFrag acc[2][4];
    #pragma unroll
    for (int i = 0; i < 2; i++)
        #pragma unroll
        for (int j = 0; j < 4; j++) wmma::fill_fragment(acc[i][j], 0.0f);
    size_t woff = OFF_EW1 + (size_t)e * CC * FF;
    wmma_core(g_h_hi, g_h_lo, g_w_hi + woff, g_w_lo + woff, s_tok, 0, FF, CC, 0, col0, S, acc);
    stage_acc(acc, Cs, tid);
    #pragma unroll
    for (int u = 0; u < 16; u++) {
        int f = tid + u * 256;
        int r = f >> 5, c = (f & 31) * 4;
        if (row0 + r >= cnt) continue;
        int gc = col0 + c;
        float4 v = *(float4*)&Cs[r][c];
        float vv[4] = {v.x, v.y, v.z, v.w};
        __align__(8) __nv_bfloat16 hh[4], ll[4];
        #pragma unroll
        for (int j = 0; j < 4; j++) {
            float xx = vv[j] + eb1[e * FF + gc + j];
            float uu = 0.7978845608028654f * (xx + 0.044715f * xx * xx * xx);
            float ge = 0.5f * xx * (1.0f + tanhf(uu));
            split1(ge, hh[j], ll[j]);
        }
        size_t idx = ((size_t)e * EROWS + row0 + r) * FF + gc;
        *(uint2*)(g_mid_hi + idx) = *(uint2*)hh;
        *(uint2*)(g_mid_lo + idx) = *(uint2*)ll;
    }
}

// ---------------- expert GEMM 2 ----------------
__global__ void __launch_bounds__(256) egemm2_kernel(const float* __restrict__ eb2) {
    int e = blockIdx.z;
    int cnt = g_count[e];
    int row0 = blockIdx.y * 128;
    if (row0 >= cnt) return;
    int col0 = blockIdx.x * 128;
    extern __shared__ char smraw[];
    SmemGemm* S = (SmemGemm*)smraw;
    float (*Cs)[CPAD] = (float(*)[CPAD])smraw;
    int tid = threadIdx.x;
    AccFrag acc[2][4];
    #pragma unroll
    for (int i = 0; i < 2; i++)
        #pragma unroll
        for (int j = 0; j < 4; j++) wmma::fill_fragment(acc[i][j], 0.0f);
    size_t woff = OFF_EW2 + (size_t)e * FF * CC;
    wmma_core(g_mid_hi + (size_t)e * EROWS * FF, g_mid_lo + (size_t)e * EROWS * FF,
              g_w_hi + woff, g_w_lo + woff, nullptr, cnt, CC, FF, row0, col0, S, acc);
    stage_acc(acc, Cs, tid);
    #pragma unroll
    for (int u = 0; u < 16; u++) {
        int f = tid + u * 256;
        int r = f >> 5, c = (f & 31) * 4;
        if (row0 + r >= cnt) continue;
        int gc = col0 + c;
        float4 v = *(float4*)&Cs[r][c];
        v.x += eb2[e * CC + gc];     v.y += eb2[e * CC + gc + 1];
        v.z += eb2[e * CC + gc + 2]; v.w += eb2[e * CC + gc + 3];
        *(float4*)&g_eo[((size_t)e * EROWS + row0 + r) * CC + gc] = v;
    }
}

// ---------------- combine + aux ----------------
__global__ void combine_kernel(float* __restrict__ out) {
    int t = blockIdx.x;
    int tid = threadIdx.x;
    int r0 = g_tokrow[t * 2], r1 = g_tokrow[t * 2 + 1];
    float g0 = g_tokgate[t * 2], g1 = g_tokgate[t * 2 + 1];
    const float* x2 = g_x2 + (size_t)t * CC;
    const float* e0 = g_eo + (size_t)r0 * CC;
    const float* e1 = g_eo + (size_t)r1 * CC;
    float* orow = out + (size_t)t * CC;
    for (int c = tid; c < CC; c += 128)
        orow[c] = x2[c] + g0 * e0[c] + g1 * e1[c];
}

__global__ void aux_kernel(float* __restrict__ out, int out_size) {
    if (threadIdx.x == 0 && blockIdx.x == 0) {
        float a = 0.0f;
        for (int e = 0; e < EE; e++)
            a += (g_count[e] / (float)TOK) * (g_Psum[e] / (float)TOK);
        a *= (float)EE;
        if (out_size > TOK * CC) out[TOK * CC] = a;
    }
}

// ---------------- launch ----------------
extern "C" void kernel_launch(void* const* d_in, const int* in_sizes, int n_in,
                              void* d_out, int out_size) {
    const float* x      = (const float*)d_in[0];
    const float* vision = (const float*)d_in[1];
    const float* ln1_g = (const float*)d_in[2];  const float* ln1_b = (const float*)d_in[3];
    const float* ln2_g = (const float*)d_in[4];  const float* ln2_b = (const float*)d_in[5];
    const float* ln3_g = (const float*)d_in[6];  const float* ln3_b = (const float*)d_in[7];
    const float* sa_wq = (const float*)d_in[8];  const float* sa_bq = (const float*)d_in[9];
    const float* sa_wk = (const float*)d_in[10]; const float* sa_bk = (const float*)d_in[11];
    const float* sa_wv = (const float*)d_in[12]; const float* sa_bv = (const float*)d_in[13];
    const float* sa_wo = (const float*)d_in[14]; const float* sa_bo = (const float*)d_in[15];
    const float* ca_wq = (const float*)d_in[16]; const float* ca_bq = (const float*)d_in[17];
    const float* ca_wk = (const float*)d_in[18]; const float* ca_bk = (const float*)d_in[19];
    const float* ca_wv = (const float*)d_in[20]; const float* ca_bv = (const float*)d_in[21];
    const float* ca_wo = (const float*)d_in[22]; const float* ca_bo = (const float*)d_in[23];
    const float* rw    = (const float*)d_in[24]; const float* rb    = (const float*)d_in[25];
    const float* ew1   = (const float*)d_in[26]; const float* eb1   = (const float*)d_in[27];
    const float* ew2   = (const float*)d_in[28]; const float* eb2   = (const float*)d_in[29];
    float* out = (float*)d_out;

    float *p_h, *p_x1, *p_x2;
    __nv_bfloat16 *p_hh, *p_hl, *p_qh, *p_ql, *p_kh, *p_kl, *p_vh_, *p_vl_;
    __nv_bfloat16 *p_k2h, *p_k2l, *p_v2h, *p_v2l;
    __nv_bfloat16 *p_ath, *p_atl, *p_vih, *p_vil, *p_wh, *p_wl;
    cudaGetSymbolAddress((void**)&p_h,  g_h);
    cudaGetSymbolAddress((void**)&p_x1, g_x1);
    cudaGetSymbolAddress((void**)&p_x2, g_x2);
    cudaGetSymbolAddress((void**)&p_hh, g_h_hi);
    cudaGetSymbolAddress((void**)&p_hl, g_h_lo);
    cudaGetSymbolAddress((void**)&p_qh, g_q_hi);
    cudaGetSymbolAddress((void**)&p_ql, g_q_lo);
    cudaGetSymbolAddress((void**)&p_kh, g_k_hi);
    cudaGetSymbolAddress((void**)&p_kl, g_k_lo);
    cudaGetSymbolAddress((void**)&p_vh_, g_v_hi);
    cudaGetSymbolAddress((void**)&p_vl_, g_v_lo);
    cudaGetSymbolAddress((void**)&p_k2h, g_k2_hi);
    cudaGetSymbolAddress((void**)&p_k2l, g_k2_lo);
    cudaGetSymbolAddress((void**)&p_v2h, g_v2_hi);
    cudaGetSymbolAddress((void**)&p_v2l, g_v2_lo);
    cudaGetSymbolAddress((void**)&p_ath, g_att_hi);
    cudaGetSymbolAddress((void**)&p_atl, g_att_lo);
    cudaGetSymbolAddress((void**)&p_vih, g_vis_hi);
    cudaGetSymbolAddress((void**)&p_vil, g_vis_lo);
    cudaGetSymbolAddress((void**)&p_wh, g_w_hi);
    cudaGetSymbolAddress((void**)&p_wl, g_w_lo);

    const int gemm_smem = GEMM_SMEM_BYTES;
    cudaFuncSetAttribute(gemm128,       cudaFuncAttributeMaxDynamicSharedMemorySize, gemm_smem);
    cudaFuncSetAttribute(kvgemm128,     cudaFuncAttributeMaxDynamicSharedMemorySize, gemm_smem);
    cudaFuncSetAttribute(egemm1_kernel, cudaFuncAttributeMaxDynamicSharedMemorySize, gemm_smem);
    cudaFuncSetAttribute(egemm2_kernel, cudaFuncAttributeMaxDynamicSharedMemorySize, gemm_smem);

    // lazily-created side streams + events (host objects only; identical work graph every call)
    static cudaStream_t s1 = nullptr, s2 = nullptr;
    static cudaEvent_t evF = nullptr, evB = nullptr, evKV = nullptr, evLn1 = nullptr;
    if (!s1) {
        cudaStreamCreateWithFlags(&s1, cudaStreamNonBlocking);
        cudaStreamCreateWithFlags(&s2, cudaStreamNonBlocking);
        cudaEventCreateWithFlags(&evF,   cudaEventDisableTiming);
        cudaEventCreateWithFlags(&evB,   cudaEventDisableTiming);
        cudaEventCreateWithFlags(&evKV,  cudaEventDisableTiming);
        cudaEventCreateWithFlags(&evLn1, cudaEventDisableTiming);
    }

    dim3 gC(CC / 128, TOK / 128);
    dim3 gKVsa(2, TOK / 128);
    dim3 gKVca(2, (BB * MV) / 128);
    dim3 gAtt(NN / 128, HH, BB);

    auto conv = [&](const float* src, size_t off, int n, cudaStream_t st) {
        conv_kernel<<<(n / 4 + 255) / 256, 256, 0, st>>>(src, p_wh + off, p_wl + off, n);
    };

    // ---- fork s1: everything independent of block 1 ----
    cudaEventRecord(evF, 0);
    cudaStreamWaitEvent(s1, evF, 0);
    conv(ca_wq, OFF_CAWQ, SZ_QO, s1); conv(ca_wk, OFF_CAWK, SZ_KV, s1);
    conv(ca_wv, OFF_CAWV, SZ_KV, s1); conv(ca_wo, OFF_CAWO, SZ_QO, s1);
    conv_kernel<<<(BB * MV * CC / 4 + 255) / 256, 256, 0, s1>>>(vision, p_vih, p_vil, BB * MV * CC);
    conv(ew1, OFF_EW1, EE * CC * FF, s1);
    conv(ew2, OFF_EW2, EE * FF * CC, s1);
    kvgemm128<<<gKVca, 256, gemm_smem, s1>>>(p_vih, p_vil, OFF_CAWK, ca_bk, OFF_CAWV, ca_bv,
                                             p_k2h, p_k2l, p_v2h, p_v2l, BB * MV, CC);
    cudaEventRecord(evB, s1);

    // ---- main stream: SA weight conv + block 1 ----
    conv(sa_wq, OFF_SAWQ, SZ_QO, 0); conv(sa_wk, OFF_SAWK, SZ_KV, 0);
    conv(sa_wv, OFF_SAWV, SZ_KV, 0); conv(sa_wo, OFF_SAWO, SZ_QO, 0);
    ln_kernel<<<TOK, 256>>>(x, ln1_g, ln1_b, nullptr, p_hh, p_hl);
    cudaEventRecord(evLn1, 0);
    cudaStreamWaitEvent(s2, evLn1, 0);
    kvgemm128<<<gKVsa, 256, gemm_smem, s2>>>(p_hh, p_hl, OFF_SAWK, sa_bk, OFF_SAWV, sa_bv,
                                             p_kh, p_kl, p_vh_, p_vl_, TOK, CC);
    cudaEventRecord(evKV, s2);
    gemm128<<<gC, 256, gemm_smem>>>(p_hh, p_hl, OFF_SAWQ, sa_bq, nullptr,
                                    nullptr, p_qh, p_ql, TOK, CC, CC);
    cudaStreamWaitEvent(0, evKV, 0);
    flash_mma<<<gAtt, 256>>>(p_qh, p_ql, p_kh, p_kl, p_vh_, p_vl_, p_ath, p_atl, NN, 1);
    gemm128<<<gC, 256, gemm_smem>>>(p_ath, p_atl, OFF_SAWO, sa_bo, x,
                                    p_x1, nullptr, nullptr, TOK, CC, CC);

    // ---- block 2: CA (join s1 before first consumer of its outputs) ----
    ln_kernel<<<TOK, 256>>>(p_x1, ln2_g, ln2_b, nullptr, p_hh, p_hl);
    cudaStreamWaitEvent(0, evB, 0);
    gemm128<<<gC, 256, gemm_smem>>>(p_hh, p_hl, OFF_CAWQ, ca_bq, nullptr,
                                    nullptr, p_qh, p_ql, TOK, CC, CC);
    flash_mma<<<gAtt, 256>>>(p_qh, p_ql, p_k2h, p_k2l, p_v2h, p_v2l, p_ath, p_atl, MV, 0);
    gemm128<<<gC, 256, gemm_smem>>>(p_ath, p_atl, OFF_CAWO, ca_bo, p_x1,
                                    p_x2, nullptr, nullptr, TOK, CC, CC);

    // ---- block 3: MoE ----
    ln_kernel<<<TOK, 256>>>(p_x2, ln3_g, ln3_b, p_h, p_hh, p_hl);
    zero_kernel<<<1, 32>>>();
    router_kernel<<<TOK / 256, 256>>>(rw, rb);
    egemm1_kernel<<<dim3(FF / 128, EROWS / 128, EE), 256, gemm_smem>>>(eb1);
    egemm2_kernel<<<dim3(CC / 128, EROWS / 128, EE), 256, gemm_smem>>>(eb2);
    combine_kernel<<<TOK, 128>>>(out);
    aux_kernel<<<1, 1>>>(out, out_size);
}

// round 15
// speedup vs baseline: 2.3378x; 2.2642x over previous
#include <cuda_runtime.h>
#include <cuda_bf16.h>
#include <cuda_fp16.h>
#include <mma.h>
#include <math.h>
#include <cstdint>

using namespace nvcuda;

// ---------------- problem constants ----------------
#define BB 4
#define NN 2048
#define MV 576
#define CC 512
#define HH 8
#define KVH 2
#define DD 64
#define EE 8
#define TOPK 2
#define FF 2048
#define TOK (BB*NN)
#define KVDIM (KVH*DD)       // 128
#define EROWS 8192

// weight buffer offsets (elements)
#define SZ_QO (CC*CC)
#define SZ_KV (CC*KVDIM)
#define OFF_SAWQ 0
#define OFF_SAWK (OFF_SAWQ+SZ_QO)
#define OFF_SAWV (OFF_SAWK+SZ_KV)
#define OFF_SAWO (OFF_SAWV+SZ_KV)
#define OFF_CAWQ (OFF_SAWO+SZ_QO)
#define OFF_CAWK (OFF_CAWQ+SZ_QO)
#define OFF_CAWV (OFF_CAWK+SZ_KV)
#define OFF_CAWO (OFF_CAWV+SZ_KV)
#define OFF_EW1  (OFF_CAWO+SZ_QO)
#define OFF_EW2  (OFF_EW1 + (size_t)EE*CC*FF)
#define WTOT     (OFF_EW2 + (size_t)EE*FF*CC)

// ---------------- static scratch ----------------
__device__ float g_h  [(size_t)TOK*CC];     // fp32 LN out (router)
__device__ float g_x1 [(size_t)TOK*CC];
__device__ float g_x2 [(size_t)TOK*CC];
__device__ float g_eo [(size_t)EE*EROWS*CC];
__device__ __half g_hx [(size_t)TOK*CC];
__device__ __half g_qx [(size_t)TOK*CC];
__device__ __half g_kx [(size_t)TOK*KVDIM];
__device__ __half g_vx [(size_t)TOK*KVDIM];
__device__ __half g_k2x[(size_t)BB*MV*KVDIM];
__device__ __half g_v2x[(size_t)BB*MV*KVDIM];
__device__ __half g_atx[(size_t)TOK*CC];
__device__ __half g_vix[(size_t)BB*MV*CC];
__device__ __half g_mid[(size_t)EE*EROWS*FF];
__device__ __half g_w  [WTOT];
__device__ int   g_count[EE];
__device__ float g_Psum[EE];
__device__ int   g_tokrow [TOK*TOPK];
__device__ float g_tokgate[TOK*TOPK];
__device__ int   g_tok_of_row[EE*EROWS];

// ---------------- helpers ----------------
__device__ __forceinline__ unsigned pk2h(float lo, float hi) {
    __half2 t = __floats2half2_rn(lo, hi);
    return *(unsigned*)&t;
}
__device__ __forceinline__ void mma16816(float* c, const unsigned* a, const unsigned* b) {
    asm volatile(
        "mma.sync.aligned.m16n8k16.row.col.f32.f16.f16.f32 "
        "{%0,%1,%2,%3},{%4,%5,%6,%7},{%8,%9},{%0,%1,%2,%3};"
        : "+f"(c[0]), "+f"(c[1]), "+f"(c[2]), "+f"(c[3])
        : "r"(a[0]), "r"(a[1]), "r"(a[2]), "r"(a[3]), "r"(b[0]), "r"(b[1]));
}
// 16B async copy; zero-fill when !valid
__device__ __forceinline__ void cp16(void* dst, const void* src, bool valid) {
    unsigned d = (unsigned)__cvta_generic_to_shared(dst);
    int sz = valid ? 16 : 0;
    asm volatile("cp.async.cg.shared.global [%0], [%1], 16, %2;\n" :: "r"(d), "l"(src), "r"(sz));
}
#define CP_COMMIT asm volatile("cp.async.commit_group;\n" ::: "memory")
#define CP_WAIT0  asm volatile("cp.async.wait_group 0;\n" ::: "memory")
#define CP_WAIT1  asm volatile("cp.async.wait_group 1;\n" ::: "memory")

// ---------------- fp32 -> fp16 conversion ----------------
__global__ void conv_kernel(const float* __restrict__ src, __half* __restrict__ dst, int n) {
    int i = (blockIdx.x * blockDim.x + threadIdx.x) * 4;
    if (i >= n) return;
    float4 v = *(const float4*)(src + i);
    __align__(8) __half h[4];
    h[0] = __float2half(v.x); h[1] = __float2half(v.y);
    h[2] = __float2half(v.z); h[3] = __float2half(v.w);
    *(uint2*)(dst + i) = *(uint2*)h;
}

// ---------------- LayerNorm (optional fp32 + fp16 out) ----------------
__global__ void ln_kernel(const float* __restrict__ x, const float* __restrict__ g,
                          const float* __restrict__ b, float* __restrict__ o,
                          __half* __restrict__ oh) {
    int t = blockIdx.x;
    int tid = threadIdx.x;
    const float* xr = x + (size_t)t * CC;
    float v0 = xr[tid], v1 = xr[tid + 256];
    __shared__ float red[256];
    red[tid] = v0 + v1; __syncthreads();
    for (int off = 128; off > 0; off >>= 1) {
        if (tid < off) red[tid] += red[tid + off];
        __syncthreads();
    }
    float mu = red[0] * (1.0f / CC);
    __syncthreads();
    float d0 = v0 - mu, d1 = v1 - mu;
    red[tid] = d0 * d0 + d1 * d1; __syncthreads();
    for (int off = 128; off > 0; off >>= 1) {
        if (tid < off) red[tid] += red[tid + off];
        __syncthreads();
    }
    float rstd = rsqrtf(red[0] * (1.0f / CC) + 1e-6f);
    size_t base = (size_t)t * CC;
    float r0 = d0 * rstd * g[tid]       + b[tid];
    float r1 = d1 * rstd * g[tid + 256] + b[tid + 256];
    if (o) { o[base + tid] = r0; o[base + tid + 256] = r1; }
    oh[base + tid]       = __float2half(r0);
    oh[base + tid + 256] = __float2half(r1);
}

// ---------------- wmma fp16 GEMM core, 3-stage cp.async pipeline ----------------
#define APAD 40
#define BPAD 136
#define CPAD 132
struct SmemGemm {
    __half Ah[3][128][APAD];
    __half Bh[3][32][BPAD];
};
#define GEMM_SMEM_BYTES (128*CPAD*4)   // 67,584 Cs staging > sizeof(SmemGemm)=56,832

typedef wmma::fragment<wmma::accumulator, 16, 16, 16, float> AccFrag;

__device__ __forceinline__ void wmma_core(
        const __half* __restrict__ Ahg, const __half* __restrict__ Bhg,
        const int* __restrict__ tokidx,
        int Mr, int Nc, int Kd, int row0, int col0,
        SmemGemm* S, AccFrag (&acc)[2][4]) {
    int tid = threadIdx.x;
    int w = tid >> 5, wm = w & 3, wn = w >> 2;
    int ra = tid >> 1, kc = (tid & 1) * 16;
    int rb = tid >> 3, cb = (tid & 7) * 16;

    size_t arow; bool avalid;
    if (tokidx) {
        int tok = tokidx[ra];
        avalid = (tok >= 0);
        arow = (size_t)(avalid ? tok : 0) * Kd;
    } else {
        int gr = row0 + ra;
        avalid = (gr < Mr);
        arow = (size_t)(avalid ? gr : 0) * Kd;
    }

    int nch = Kd / 32;
    auto issue = [&](int c, int buf) {
        int k0 = c * 32;
        size_t ab = arow + k0 + kc;
        cp16(&S->Ah[buf][ra][kc],     Ahg + ab,     avalid);
        cp16(&S->Ah[buf][ra][kc + 8], Ahg + ab + 8, avalid);
        size_t bb = (size_t)(k0 + rb) * Nc + col0 + cb;
        cp16(&S->Bh[buf][rb][cb],     Bhg + bb,     true);
        cp16(&S->Bh[buf][rb][cb + 8], Bhg + bb + 8, true);
        CP_COMMIT;
    };

    issue(0, 0);
    issue(1, 1);
    int buf = 0, nbuf = 2;
    #pragma unroll 1
    for (int c = 0; c < nch; c++) {
        CP_WAIT1;
        __syncthreads();
        if (c + 2 < nch) issue(c + 2, nbuf);
        #pragma unroll
        for (int ks = 0; ks < 2; ks++) {
            wmma::fragment<wmma::matrix_a, 16,16,16, __half, wmma::row_major> ah[2];
            wmma::fragment<wmma::matrix_b, 16,16,16, __half, wmma::row_major> bh[4];
            #pragma unroll
            for (int i = 0; i < 2; i++)
                wmma::load_matrix_sync(ah[i], &S->Ah[buf][wm*32 + i*16][ks*16], APAD);
            #pragma unroll
            for (int j = 0; j < 4; j++)
                wmma::load_matrix_sync(bh[j], &S->Bh[buf][ks*16][wn*64 + j*16], BPAD);
            #pragma unroll
            for (int i = 0; i < 2; i++)
                #pragma unroll
                for (int j = 0; j < 4; j++)
                    wmma::mma_sync(acc[i][j], ah[i], bh[j], acc[i][j]);
        }
        buf = (buf == 2) ? 0 : buf + 1;
        nbuf = (nbuf == 2) ? 0 : nbuf + 1;
    }
    __syncthreads();  // smem stages done before Cs aliasing
}

__device__ __forceinline__ void stage_acc(AccFrag (&acc)[2][4], float (*Cs)[CPAD], int tid) {
    int w = tid >> 5, wm = w & 3, wn = w >> 2;
    #pragma unroll
    for (int i = 0; i < 2; i++)
        #pragma unroll
        for (int j = 0; j < 4; j++)
            wmma::store_matrix_sync(&Cs[wm*32 + i*16][wn*64 + j*16], acc[i][j],
                                    CPAD, wmma::mem_row_major);
    __syncthreads();
}

// ---------------- generic GEMM: fp32 out (bias/resid) OR fp16 out ----------------
__global__ void __launch_bounds__(256) gemm128(
        const __half* __restrict__ Ahg,
        int woff, const float* __restrict__ bias, const float* __restrict__ resid,
        float* __restrict__ out, __half* __restrict__ oh,
        int Mr, int Nc, int Kd) {
    extern __shared__ char smraw[];
    SmemGemm* S = (SmemGemm*)smraw;
    float (*Cs)[CPAD] = (float(*)[CPAD])smraw;
    int tid = threadIdx.x;
    int row0 = blockIdx.y * 128, col0 = blockIdx.x * 128;
    AccFrag acc[2][4];
    #pragma unroll
    for (int i = 0; i < 2; i++)
        #pragma unroll
        for (int j = 0; j < 4; j++) wmma::fill_fragment(acc[i][j], 0.0f);
    wmma_core(Ahg, g_w + woff, nullptr, Mr, Nc, Kd, row0, col0, S, acc);
    stage_acc(acc, Cs, tid);
    #pragma unroll
    for (int u = 0; u < 16; u++) {
        int f = tid + u * 256;
        int r = f >> 5, c = (f & 31) * 4;
        int gr = row0 + r;
        if (gr >= Mr) continue;
        int gc = col0 + c;
        float4 v = *(float4*)&Cs[r][c];
        if (bias) { v.x += bias[gc]; v.y += bias[gc+1]; v.z += bias[gc+2]; v.w += bias[gc+3]; }
        if (resid) {
            float4 rr = *(const float4*)(resid + (size_t)gr * Nc + gc);
            v.x += rr.x; v.y += rr.y; v.z += rr.z; v.w += rr.w;
        }
        if (out) {
            *(float4*)(out + (size_t)gr * Nc + gc) = v;
        } else {
            __align__(8) __half hh[4];
            hh[0] = __float2half(v.x); hh[1] = __float2half(v.y);
            hh[2] = __float2half(v.z); hh[3] = __float2half(v.w);
            *(uint2*)(oh + (size_t)gr * Nc + gc) = *(uint2*)hh;
        }
    }
}

// ---------------- fused K+V projection -> fp16 ----------------
__global__ void __launch_bounds__(256) kvgemm128(
        const __half* __restrict__ Ahg,
        int woffk, const float* __restrict__ bk,
        int woffv, const float* __restrict__ bv,
        __half* __restrict__ okh, __half* __restrict__ ovh,
        int Mr, int Kd) {
    extern __shared__ char smraw[];
    SmemGemm* S = (SmemGemm*)smraw;
    float (*Cs)[CPAD] = (float(*)[CPAD])smraw;
    int woff          = (blockIdx.x == 0) ? woffk : woffv;
    const float* bias = (blockIdx.x == 0) ? bk : bv;
    __half* oh        = (blockIdx.x == 0) ? okh : ovh;
    int tid = threadIdx.x;
    int row0 = blockIdx.y * 128;
    AccFrag acc[2][4];
    #pragma unroll
    for (int i = 0; i < 2; i++)
        #pragma unroll
        for (int j = 0; j < 4; j++) wmma::fill_fragment(acc[i][j], 0.0f);
    wmma_core(Ahg, g_w + woff, nullptr, Mr, KVDIM, Kd, row0, 0, S, acc);
    stage_acc(acc, Cs, tid);
    #pragma unroll
    for (int u = 0; u < 16; u++) {
        int f = tid + u * 256;
        int r = f >> 5, c = (f & 31) * 4;
        int gr = row0 + r;
        if (gr >= Mr) continue;
        float4 v = *(float4*)&Cs[r][c];
        v.x += bias[c]; v.y += bias[c+1]; v.z += bias[c+2]; v.w += bias[c+3];
        __align__(8) __half hh[4];
        hh[0] = __float2half(v.x); hh[1] = __float2half(v.y);
        hh[2] = __float2half(v.z); hh[3] = __float2half(v.w);
        *(uint2*)(oh + (size_t)gr * KVDIM + c) = *(uint2*)hh;
    }
}

// ---------------- FA2 flash attention: mma.m16n8k16 fp16 ----------------
#define KPAD 72
__global__ void __launch_bounds__(256) flash_mma(
        const __half* __restrict__ qh, const __half* __restrict__ kh,
        const __half* __restrict__ vh, __half* __restrict__ oh,
        int n_kv, int causal) {
    __shared__ __half Kh[64][KPAD], Vth[64][KPAD];
    int qt = blockIdx.x, h = blockIdx.y, b = blockIdx.z;
    int g = h >> 2;
    int tid = threadIdx.x, w = tid >> 5, lane = tid & 31;
    int r0 = lane >> 2, tq = lane & 3;
    int qrow = qt * 128 + w * 16 + r0;

    unsigned qah[4][4];
    {
        const __half* q0 = qh + ((size_t)(b * NN + qrow)) * CC + h * DD;
        const __half* q1 = qh + ((size_t)(b * NN + qrow + 8)) * CC + h * DD;
        #pragma unroll
        for (int ks = 0; ks < 4; ks++) {
            int c = ks * 16 + tq * 2;
            qah[ks][0] = *(const unsigned*)(q0 + c);
            qah[ks][1] = *(const unsigned*)(q1 + c);
            qah[ks][2] = *(const unsigned*)(q0 + c + 8);
            qah[ks][3] = *(const unsigned*)(q1 + c + 8);
        }
    }

    float m0 = -1e30f, m1 = -1e30f, l0 = 0.0f, l1 = 0.0f;
    float o[8][4] = {};

    int key_l = tid >> 2, dseg = (tid & 3) * 16;
    int nkt = causal ? (2 * qt + 2) : (n_kv / 64);
    for (int kt = 0; kt < nkt; kt++) {
        __syncthreads();
        {
            size_t base = ((size_t)(b * n_kv + kt * 64 + key_l)) * KVDIM + g * DD + dseg;
            *(uint4*)&Kh[key_l][dseg]     = *(const uint4*)(kh + base);
            *(uint4*)&Kh[key_l][dseg + 8] = *(const uint4*)(kh + base + 8);
            const __half* vp = vh + base;
            #pragma unroll
            for (int i = 0; i < 16; i++)
                Vth[dseg + i][key_l] = vp[i];
        }
        __syncthreads();

        float sc[8][4] = {};
        #pragma unroll
        for (int nt = 0; nt < 8; nt++) {
            int krow = nt * 8 + r0;
            #pragma unroll
            for (int ks = 0; ks < 4; ks++) {
                int c = ks * 16 + tq * 2;
                unsigned bh[2];
                bh[0] = *(const unsigned*)&Kh[krow][c];
                bh[1] = *(const unsigned*)&Kh[krow][c + 8];
                mma16816(sc[nt], qah[ks], bh);
            }
        }
        bool maskit = causal && (kt >= 2 * qt);
        #pragma unroll
        for (int nt = 0; nt < 8; nt++) {
            #pragma unroll
            for (int j = 0; j < 4; j++) {
                float v = sc[nt][j] * 0.125f;
                if (maskit) {
                    int col = kt * 64 + nt * 8 + tq * 2 + (j & 1);
                    int row = qt * 128 + w * 16 + r0 + ((j >> 1) ? 8 : 0);
                    if (col > row) v = -1e9f;
                }
                sc[nt][j] = v;
            }
        }
        float rm0 = -1e30f, rm1 = -1e30f;
        #pragma unroll
        for (int nt = 0; nt < 8; nt++) {
            rm0 = fmaxf(rm0, fmaxf(sc[nt][0], sc[nt][1]));
            rm1 = fmaxf(rm1, fmaxf(sc[nt][2], sc[nt][3]));
        }
        #pragma unroll
        for (int off = 1; off < 4; off <<= 1) {
            rm0 = fmaxf(rm0, __shfl_xor_sync(0xffffffffu, rm0, off));
            rm1 = fmaxf(rm1, __shfl_xor_sync(0xffffffffu, rm1, off));
        }
        float mn0 = fmaxf(m0, rm0), mn1 = fmaxf(m1, rm1);
        float al0 = __expf(m0 - mn0), al1 = __expf(m1 - mn1);
        m0 = mn0; m1 = mn1;
        float rs0 = 0.0f, rs1 = 0.0f;
        #pragma unroll
        for (int nt = 0; nt < 8; nt++) {
            sc[nt][0] = __expf(sc[nt][0] - mn0);
            sc[nt][1] = __expf(sc[nt][1] - mn0);
            sc[nt][2] = __expf(sc[nt][2] - mn1);
            sc[nt][3] = __expf(sc[nt][3] - mn1);
            rs0 += sc[nt][0] + sc[nt][1];
            rs1 += sc[nt][2] + sc[nt][3];
        }
        #pragma unroll
        for (int off = 1; off < 4; off <<= 1) {
            rs0 += __shfl_xor_sync(0xffffffffu, rs0, off);
            rs1 += __shfl_xor_sync(0xffffffffu, rs1, off);
        }
        l0 = l0 * al0 + rs0;
        l1 = l1 * al1 + rs1;
        #pragma unroll
        for (int nt = 0; nt < 8; nt++) {
            o[nt][0] *= al0; o[nt][1] *= al0;
            o[nt][2] *= al1; o[nt][3] *= al1;
        }
        #pragma unroll
        for (int kp = 0; kp < 4; kp++) {
            unsigned pah[4];
            pah[0] = pk2h(sc[2*kp][0],   sc[2*kp][1]);
            pah[1] = pk2h(sc[2*kp][2],   sc[2*kp][3]);
            pah[2] = pk2h(sc[2*kp+1][0], sc[2*kp+1][1]);
            pah[3] = pk2h(sc[2*kp+1][2], sc[2*kp+1][3]);
            #pragma unroll
            for (int nt = 0; nt < 8; nt++) {
                int drow = nt * 8 + r0;
                int c = kp * 16 + tq * 2;
                unsigned bh[2];
                bh[0] = *(const unsigned*)&Vth[drow][c];
                bh[1] = *(const unsigned*)&Vth[drow][c + 8];
                mma16816(o[nt], pah, bh);
            }
        }
    }
    float inv0 = 1.0f / l0, inv1 = 1.0f / l1;
    size_t base0 = ((size_t)(b * NN + qrow)) * CC + h * DD;
    size_t base1 = ((size_t)(b * NN + qrow + 8)) * CC + h * DD;
    #pragma unroll
    for (int nt = 0; nt < 8; nt++) {
        int d = nt * 8 + tq * 2;
        *(unsigned*)(oh + base0 + d) = pk2h(o[nt][0] * inv0, o[nt][1] * inv0);
        *(unsigned*)(oh + base1 + d) = pk2h(o[nt][2] * inv1, o[nt][3] * inv1);
    }
}

// ---------------- MoE routing ----------------
__global__ void zero_kernel() {
    int t = threadIdx.x;
    if (t < EE) { g_count[t] = 0; g_Psum[t] = 0.0f; }
}

__global__ void router_kernel(const float* __restrict__ rw, const float* __restrict__ rb) {
    __shared__ float sP[EE];
    int tid = threadIdx.x;
    if (tid < EE) sP[tid] = 0.0f;
    __syncthreads();
    int t = blockIdx.x * blockDim.x + tid;
    float logit[EE];
    const float* hrow = g_h + (size_t)t * CC;
    #pragma unroll
    for (int e = 0; e < EE; e++) logit[e] = rb[e];
    for (int k = 0; k < CC; k++) {
        float hv = hrow[k];
        const float* wr = rw + k * EE;
        #pragma unroll
        for (int e = 0; e < EE; e++) logit[e] += hv * wr[e];
    }
    float mx = logit[0];
    #pragma unroll
    for (int e = 1; e < EE; e++) mx = fmaxf(mx, logit[e]);
    float p[EE], ps = 0.0f;
    #pragma unroll
    for (int e = 0; e < EE; e++) { p[e] = __expf(logit[e] - mx); ps += p[e]; }
    float invs = 1.0f / ps;
    #pragma unroll
    for (int e = 0; e < EE; e++) p[e] *= invs;
    int i0 = 0;
    #pragma unroll
    for (int e = 1; e < EE; e++) if (p[e] > p[i0]) i0 = e;
    int i1 = (i0 == 0) ? 1 : 0;
    #pragma unroll
    for (int e = 0; e < EE; e++) if (e != i0 && p[e] > p[i1]) i1 = e;
    float gs = p[i0] + p[i1];
    float g0 = p[i0] / gs, g1 = p[i1] / gs;
    int s0 = atomicAdd(&g_count[i0], 1);
    int s1 = atomicAdd(&g_count[i1], 1);
    int r0 = i0 * EROWS + s0, r1 = i1 * EROWS + s1;
    g_tok_of_row[r0] = t; g_tok_of_row[r1] = t;
    g_tokrow[t * 2] = r0; g_tokrow[t * 2 + 1] = r1;
    g_tokgate[t * 2] = g0; g_tokgate[t * 2 + 1] = g1;
    #pragma unroll
    for (int e = 0; e < EE; e++) atomicAdd(&sP[e], p[e]);
    __syncthreads();
    if (tid < EE) atomicAdd(&g_Psum[tid], sP[tid]);
}

// ---------------- expert GEMM 1 (gathered A, GELU -> mid fp16) ----------------
__global__ void __launch_bounds__(256) egemm1_kernel(const float* __restrict__ eb1) {
    int e = blockIdx.z;
    int cnt = g_count[e];
    int row0 = blockIdx.y * 128;
    if (row0 >= cnt) return;
    int col0 = blockIdx.x * 128;
    extern __shared__ char smraw[];
    SmemGemm* S = (SmemGemm*)smraw;
    float (*Cs)[CPAD] = (float(*)[CPAD])smraw;
    __shared__ int s_tok[128];
    int tid = threadIdx.x;
    if (tid < 128) {
        int gr = row0 + tid;
        s_tok[tid] = (gr < cnt) ? g_tok_of_row[e * EROWS + gr] : -1;
    }
    __syncthreads();
    AccFrag acc[2][4];
    #pragma unroll
    for (int i = 0; i < 2; i++)
        #pragma unroll
        for (int j = 0; j < 4; j++) wmma::fill_fragment(acc[i][j], 0.0f);
    size_t woff = OFF_EW1 + (size_t)e * CC * FF;
    wmma_core(g_hx, g_w + woff, s_tok, 0, FF, CC, 0, col0, S, acc);
    stage_acc(acc, Cs, tid);
    #pragma unroll
    for (int u = 0; u < 16; u++) {
        int f = tid + u * 256;
        int r = f >> 5, c = (f & 31) * 4;
        if (row0 + r >= cnt) continue;
        int gc = col0 + c;
        float4 v = *(float4*)&Cs[r][c];
        float vv[4] = {v.x, v.y, v.z, v.w};
        __align__(8) __half hh[4];
        #pragma unroll
        for (int j = 0; j < 4; j++) {
            float xx = vv[j] + eb1[e * FF + gc + j];
            float uu = 0.7978845608028654f * (xx + 0.044715f * xx * xx * xx);
            float ge = 0.5f * xx * (1.0f + tanhf(uu));
            hh[j] = __float2half(ge);
        }
        size_t idx = ((size_t)e * EROWS + row0 + r) * FF + gc;
        *(uint2*)(g_mid + idx) = *(uint2*)hh;
    }
}

// ---------------- expert GEMM 2 ----------------
__global__ void __launch_bounds__(256) egemm2_kernel(const float* __restrict__ eb2) {
    int e = blockIdx.z;
    int cnt = g_count[e];
    int row0 = blockIdx.y * 128;
    if (row0 >= cnt) return;
    int col0 = blockIdx.x * 128;
    extern __shared__ char smraw[];
    SmemGemm* S = (SmemGemm*)smraw;
    float (*Cs)[CPAD] = (float(*)[CPAD])smraw;
    int tid = threadIdx.x;
    AccFrag acc[2][4];
    #pragma unroll
    for (int i = 0; i < 2; i++)
        #pragma unroll
        for (int j = 0; j < 4; j++) wmma::fill_fragment(acc[i][j], 0.0f);
    size_t woff = OFF_EW2 + (size_t)e * FF * CC;
    wmma_core(g_mid + (size_t)e * EROWS * FF, g_w + woff, nullptr, cnt, CC, FF, row0, col0, S, acc);
    stage_acc(acc, Cs, tid);
    #pragma unroll
    for (int u = 0; u < 16; u++) {
        int f = tid + u * 256;
        int r = f >> 5, c = (f & 31) * 4;
        if (row0 + r >= cnt) continue;
        int gc = col0 + c;
        float4 v = *(float4*)&Cs[r][c];
        v.x += eb2[e * CC + gc];     v.y += eb2[e * CC + gc + 1];
        v.z += eb2[e * CC + gc + 2]; v.w += eb2[e * CC + gc + 3];
        *(float4*)&g_eo[((size_t)e * EROWS + row0 + r) * CC + gc] = v;
    }
}

// ---------------- combine + aux ----------------
__global__ void combine_kernel(float* __restrict__ out) {
    int t = blockIdx.x;
    int tid = threadIdx.x;
    int r0 = g_tokrow[t * 2], r1 = g_tokrow[t * 2 + 1];
    float g0 = g_tokgate[t * 2], g1 = g_tokgate[t * 2 + 1];
    const float* x2 = g_x2 + (size_t)t * CC;
    const float* e0 = g_eo + (size_t)r0 * CC;
    const float* e1 = g_eo + (size_t)r1 * CC;
    float* orow = out + (size_t)t * CC;
    for (int c = tid; c < CC; c += 128)
        orow[c] = x2[c] + g0 * e0[c] + g1 * e1[c];
}

__global__ void aux_kernel(float* __restrict__ out, int out_size) {
    if (threadIdx.x == 0 && blockIdx.x == 0) {
        float a = 0.0f;
        for (int e = 0; e < EE; e++)
            a += (g_count[e] / (float)TOK) * (g_Psum[e] / (float)TOK);
        a *= (float)EE;
        if (out_size > TOK * CC) out[TOK * CC] = a;
    }
}

// ---------------- launch ----------------
extern "C" void kernel_launch(void* const* d_in, const int* in_sizes, int n_in,
                              void* d_out, int out_size) {
    const float* x      = (const float*)d_in[0];
    const float* vision = (const float*)d_in[1];
    const float* ln1_g = (const float*)d_in[2];  const float* ln1_b = (const float*)d_in[3];
    const float* ln2_g = (const float*)d_in[4];  const float* ln2_b = (const float*)d_in[5];
    const float* ln3_g = (const float*)d_in[6];  const float* ln3_b = (const float*)d_in[7];
    const float* sa_wq = (const float*)d_in[8];  const float* sa_bq = (const float*)d_in[9];
    const float* sa_wk = (const float*)d_in[10]; const float* sa_bk = (const float*)d_in[11];
    const float* sa_wv = (const float*)d_in[12]; const float* sa_bv = (const float*)d_in[13];
    const float* sa_wo = (const float*)d_in[14]; const float* sa_bo = (const float*)d_in[15];
    const float* ca_wq = (const float*)d_in[16]; const float* ca_bq = (const float*)d_in[17];
    const float* ca_wk = (const float*)d_in[18]; const float* ca_bk = (const float*)d_in[19];
    const float* ca_wv = (const float*)d_in[20]; const float* ca_bv = (const float*)d_in[21];
    const float* ca_wo = (const float*)d_in[22]; const float* ca_bo = (const float*)d_in[23];
    const float* rw    = (const float*)d_in[24]; const float* rb    = (const float*)d_in[25];
    const float* ew1   = (const float*)d_in[26]; const float* eb1   = (const float*)d_in[27];
    const float* ew2   = (const float*)d_in[28]; const float* eb2   = (const float*)d_in[29];
    float* out = (float*)d_out;

    float *p_h, *p_x1, *p_x2;
    __half *p_hx, *p_qx, *p_kx, *p_vx, *p_k2x, *p_v2x, *p_atx, *p_vix, *p_w;
    cudaGetSymbolAddress((void**)&p_h,  g_h);
    cudaGetSymbolAddress((void**)&p_x1, g_x1);
    cudaGetSymbolAddress((void**)&p_x2, g_x2);
    cudaGetSymbolAddress((void**)&p_hx, g_hx);
    cudaGetSymbolAddress((void**)&p_qx, g_qx);
    cudaGetSymbolAddress((void**)&p_kx, g_kx);
    cudaGetSymbolAddress((void**)&p_vx, g_vx);
    cudaGetSymbolAddress((void**)&p_k2x, g_k2x);
    cudaGetSymbolAddress((void**)&p_v2x, g_v2x);
    cudaGetSymbolAddress((void**)&p_atx, g_atx);
    cudaGetSymbolAddress((void**)&p_vix, g_vix);
    cudaGetSymbolAddress((void**)&p_w,  g_w);

    const int gemm_smem = GEMM_SMEM_BYTES;
    cudaFuncSetAttribute(gemm128,       cudaFuncAttributeMaxDynamicSharedMemorySize, gemm_smem);
    cudaFuncSetAttribute(kvgemm128,     cudaFuncAttributeMaxDynamicSharedMemorySize, gemm_smem);
    cudaFuncSetAttribute(egemm1_kernel, cudaFuncAttributeMaxDynamicSharedMemorySize, gemm_smem);
    cudaFuncSetAttribute(egemm2_kernel, cudaFuncAttributeMaxDynamicSharedMemorySize, gemm_smem);

    static cudaStream_t s1 = nullptr, s2 = nullptr;
    static cudaEvent_t evF = nullptr, evB = nullptr, evKV = nullptr, evLn1 = nullptr;
    if (!s1) {
        cudaStreamCreateWithFlags(&s1, cudaStreamNonBlocking);
        cudaStreamCreateWithFlags(&s2, cudaStreamNonBlocking);
        cudaEventCreateWithFlags(&evF,   cudaEventDisableTiming);
        cudaEventCreateWithFlags(&evB,   cudaEventDisableTiming);
        cudaEventCreateWithFlags(&evKV,  cudaEventDisableTiming);
        cudaEventCreateWithFlags(&evLn1, cudaEventDisableTiming);
    }

    dim3 gC(CC / 128, TOK / 128);
    dim3 gKVsa(2, TOK / 128);
    dim3 gKVca(2, (BB * MV) / 128);
    dim3 gAtt(NN / 128, HH, BB);

    auto conv = [&](const float* src, size_t off, int n, cudaStream_t st) {
        conv_kernel<<<(n / 4 + 255) / 256, 256, 0, st>>>(src, p_w + off, n);
    };

    // ---- fork s1: everything independent of block 1 ----
    cudaEventRecord(evF, 0);
    cudaStreamWaitEvent(s1, evF, 0);
    conv(ca_wq, OFF_CAWQ, SZ_QO, s1); conv(ca_wk, OFF_CAWK, SZ_KV, s1);
    conv(ca_wv, OFF_CAWV, SZ_KV, s1); conv(ca_wo, OFF_CAWO, SZ_QO, s1);
    conv_kernel<<<(BB * MV * CC / 4 + 255) / 256, 256, 0, s1>>>(vision, p_vix, BB * MV * CC);
    conv(ew1, OFF_EW1, EE * CC * FF, s1);
    conv(ew2, OFF_EW2, EE * FF * CC, s1);
    kvgemm128<<<gKVca, 256, gemm_smem, s1>>>(p_vix, OFF_CAWK, ca_bk, OFF_CAWV, ca_bv,
                                             p_k2x, p_v2x, BB * MV, CC);
    cudaEventRecord(evB, s1);

    // ---- main stream: SA weight conv + block 1 ----
    conv(sa_wq, OFF_SAWQ, SZ_QO, 0); conv(sa_wk, OFF_SAWK, SZ_KV, 0);
    conv(sa_wv, OFF_SAWV, SZ_KV, 0); conv(sa_wo, OFF_SAWO, SZ_QO, 0);
    ln_kernel<<<TOK, 256>>>(x, ln1_g, ln1_b, nullptr, p_hx);
    cudaEventRecord(evLn1, 0);
    cudaStreamWaitEvent(s2, evLn1, 0);
    kvgemm128<<<gKVsa, 256, gemm_smem, s2>>>(p_hx, OFF_SAWK, sa_bk, OFF_SAWV, sa_bv,
                                             p_kx, p_vx, TOK, CC);
    cudaEventRecord(evKV, s2);
    gemm128<<<gC, 256, gemm_smem>>>(p_hx, OFF_SAWQ, sa_bq, nullptr,
                                    nullptr, p_qx, TOK, CC, CC);
    cudaStreamWaitEvent(0, evKV, 0);
    flash_mma<<<gAtt, 256>>>(p_qx, p_kx, p_vx, p_atx, NN, 1);
    gemm128<<<gC, 256, gemm_smem>>>(p_atx, OFF_SAWO, sa_bo, x,
                                    p_x1, nullptr, TOK, CC, CC);

    // ---- block 2: CA ----
    ln_kernel<<<TOK, 256>>>(p_x1, ln2_g, ln2_b, nullptr, p_hx);
    cudaStreamWaitEvent(0, evB, 0);
    gemm128<<<gC, 256, gemm_smem>>>(p_hx, OFF_CAWQ, ca_bq, nullptr,
                                    nullptr, p_qx, TOK, CC, CC);
    flash_mma<<<gAtt, 256>>>(p_qx, p_k2x, p_v2x, p_atx, MV, 0);
    gemm128<<<gC, 256, gemm_smem>>>(p_atx, OFF_CAWO, ca_bo, p_x1,
                                    p_x2, nullptr, TOK, CC, CC);

    // ---- block 3: MoE ----
    ln_kernel<<<TOK, 256>>>(p_x2, ln3_g, ln3_b, p_h, p_hx);
    zero_kernel<<<1, 32>>>();
    router_kernel<<<TOK / 256, 256>>>(rw, rb);
    egemm1_kernel<<<dim3(FF / 128, EROWS / 128, EE), 256, gemm_smem>>>(eb1);
    egemm2_kernel<<<dim3(CC / 128, EROWS / 128, EE), 256, gemm_smem>>>(eb2);
    combine_kernel<<<TOK, 128>>>(out);
    aux_kernel<<<1, 1>>>(out, out_size);
}

// round 16
// speedup vs baseline: 2.3809x; 1.0184x over previous
#include <cuda_runtime.h>
#include <cuda_bf16.h>
#include <cuda_fp16.h>
#include <math.h>
#include <cstdint>

// ---------------- problem constants ----------------
#define BB 4
#define NN 2048
#define MV 576
#define CC 512
#define HH 8
#define KVH 2
#define DD 64
#define EE 8
#define TOPK 2
#define FF 2048
#define TOK (BB*NN)
#define KVDIM (KVH*DD)       // 128
#define EROWS 8192

// weight buffer offsets (elements)
#define SZ_QO (CC*CC)
#define SZ_KV (CC*KVDIM)
#define OFF_SAWQ 0
#define OFF_SAWK (OFF_SAWQ+SZ_QO)
#define OFF_SAWV (OFF_SAWK+SZ_KV)
#define OFF_SAWO (OFF_SAWV+SZ_KV)
#define OFF_CAWQ (OFF_SAWO+SZ_QO)
#define OFF_CAWK (OFF_CAWQ+SZ_QO)
#define OFF_CAWV (OFF_CAWK+SZ_KV)
#define OFF_CAWO (OFF_CAWV+SZ_KV)
#define OFF_EW1  (OFF_CAWO+SZ_QO)
#define OFF_EW2  (OFF_EW1 + (size_t)EE*CC*FF)
#define WTOT     (OFF_EW2 + (size_t)EE*FF*CC)

// ---------------- static scratch ----------------
__device__ float g_h  [(size_t)TOK*CC];     // fp32 LN out (router)
__device__ float g_x1 [(size_t)TOK*CC];
__device__ float g_x2 [(size_t)TOK*CC];
__device__ float g_eo [(size_t)EE*EROWS*CC];
__device__ __half g_hx [(size_t)TOK*CC];
__device__ __half g_qx [(size_t)TOK*CC];
__device__ __half g_kx [(size_t)TOK*KVDIM];
__device__ __half g_vx [(size_t)TOK*KVDIM];
__device__ __half g_k2x[(size_t)BB*MV*KVDIM];
__device__ __half g_v2x[(size_t)BB*MV*KVDIM];
__device__ __half g_atx[(size_t)TOK*CC];
__device__ __half g_vix[(size_t)BB*MV*CC];
__device__ __half g_mid[(size_t)EE*EROWS*FF];
__device__ __half g_w  [WTOT];
__device__ int   g_count[EE];
__device__ float g_Psum[EE];
__device__ int   g_tokrow [TOK*TOPK];
__device__ float g_tokgate[TOK*TOPK];
__device__ int   g_tok_of_row[EE*EROWS];

// ---------------- helpers ----------------
__device__ __forceinline__ unsigned pk2h(float lo, float hi) {
    __half2 t = __floats2half2_rn(lo, hi);
    return *(unsigned*)&t;
}
__device__ __forceinline__ void mma16816(float* c, const unsigned* a, const unsigned* b) {
    asm volatile(
        "mma.sync.aligned.m16n8k16.row.col.f32.f16.f16.f32 "
        "{%0,%1,%2,%3},{%4,%5,%6,%7},{%8,%9},{%0,%1,%2,%3};"
        : "+f"(c[0]), "+f"(c[1]), "+f"(c[2]), "+f"(c[3])
        : "r"(a[0]), "r"(a[1]), "r"(a[2]), "r"(a[3]), "r"(b[0]), "r"(b[1]));
}
__device__ __forceinline__ unsigned sptr(const void* p) {
    return (unsigned)__cvta_generic_to_shared(p);
}
#define LDMX4(r, addr) \
    asm volatile("ldmatrix.sync.aligned.m8n8.x4.shared.b16 {%0,%1,%2,%3}, [%4];" \
        : "=r"((r)[0]), "=r"((r)[1]), "=r"((r)[2]), "=r"((r)[3]) : "r"(addr))
#define LDMX4T(r, addr) \
    asm volatile("ldmatrix.sync.aligned.m8n8.x4.trans.shared.b16 {%0,%1,%2,%3}, [%4];" \
        : "=r"((r)[0]), "=r"((r)[1]), "=r"((r)[2]), "=r"((r)[3]) : "r"(addr))
// 16B async copy; zero-fill when !valid
__device__ __forceinline__ void cp16(void* dst, const void* src, bool valid) {
    unsigned d = (unsigned)__cvta_generic_to_shared(dst);
    int sz = valid ? 16 : 0;
    asm volatile("cp.async.cg.shared.global [%0], [%1], 16, %2;\n" :: "r"(d), "l"(src), "r"(sz));
}
#define CP_COMMIT asm volatile("cp.async.commit_group;\n" ::: "memory")
#define CP_WAIT0  asm volatile("cp.async.wait_group 0;\n" ::: "memory")
#define CP_WAIT1  asm volatile("cp.async.wait_group 1;\n" ::: "memory")

// ---------------- fp32 -> fp16 conversion ----------------
__global__ void conv_kernel(const float* __restrict__ src, __half* __restrict__ dst, int n) {
    int i = (blockIdx.x * blockDim.x + threadIdx.x) * 4;
    if (i >= n) return;
    float4 v = *(const float4*)(src + i);
    __align__(8) __half h[4];
    h[0] = __float2half(v.x); h[1] = __float2half(v.y);
    h[2] = __float2half(v.z); h[3] = __float2half(v.w);
    *(uint2*)(dst + i) = *(uint2*)h;
}

// ---------------- LayerNorm (optional fp32 + fp16 out) ----------------
__global__ void ln_kernel(const float* __restrict__ x, const float* __restrict__ g,
                          const float* __restrict__ b, float* __restrict__ o,
                          __half* __restrict__ oh) {
    int t = blockIdx.x;
    int tid = threadIdx.x;
    const float* xr = x + (size_t)t * CC;
    float v0 = xr[tid], v1 = xr[tid + 256];
    __shared__ float red[256];
    red[tid] = v0 + v1; __syncthreads();
    for (int off = 128; off > 0; off >>= 1) {
        if (tid < off) red[tid] += red[tid + off];
        __syncthreads();
    }
    float mu = red[0] * (1.0f / CC);
    __syncthreads();
    float d0 = v0 - mu, d1 = v1 - mu;
    red[tid] = d0 * d0 + d1 * d1; __syncthreads();
    for (int off = 128; off > 0; off >>= 1) {
        if (tid < off) red[tid] += red[tid + off];
        __syncthreads();
    }
    float rstd = rsqrtf(red[0] * (1.0f / CC) + 1e-6f);
    size_t base = (size_t)t * CC;
    float r0 = d0 * rstd * g[tid]       + b[tid];
    float r1 = d1 * rstd * g[tid + 256] + b[tid + 256];
    if (o) { o[base + tid] = r0; o[base + tid + 256] = r1; }
    oh[base + tid]       = __float2half(r0);
    oh[base + tid + 256] = __float2half(r1);
}

// ---------------- raw-mma fp16 GEMM core, 3-stage cp.async pipeline ----------------
// Warp (w = tid/32): wm = w&3 -> 32-row slab; wn = w>>2 -> 64-col slab.
// Fragments via ldmatrix (A: x4, B row-major: x4.trans). Known C layout -> direct epilogue.
#define APAD 40
#define BPAD 136
struct SmemGemm {
    __half Ah[3][128][APAD];
    __half Bh[3][32][BPAD];
};
#define GEMM_SMEM_BYTES (int)sizeof(SmemGemm)   // 56,832

__device__ __forceinline__ void mma_core(
        const __half* __restrict__ Ahg, const __half* __restrict__ Bhg,
        const int* __restrict__ tokidx,
        int Mr, int Nc, int Kd, int row0, int col0,
        SmemGemm* S, float (&acc)[2][8][4]) {
    int tid = threadIdx.x;
    int w = tid >> 5, lane = tid & 31;
    int wm = w & 3, wn = w >> 2;
    int ra = tid >> 1, kc = (tid & 1) * 16;
    int rb = tid >> 3, cb = (tid & 7) * 16;
    int lr = lane & 15, lc = (lane >> 4) * 8;   // ldmatrix lane address pieces

    size_t arow; bool avalid;
    if (tokidx) {
        int tok = tokidx[ra];
        avalid = (tok >= 0);
        arow = (size_t)(avalid ? tok : 0) * Kd;
    } else {
        int gr = row0 + ra;
        avalid = (gr < Mr);
        arow = (size_t)(avalid ? gr : 0) * Kd;
    }

    int nch = Kd / 32;
    auto issue = [&](int c, int buf) {
        int k0 = c * 32;
        size_t ab = arow + k0 + kc;
        cp16(&S->Ah[buf][ra][kc],     Ahg + ab,     avalid);
        cp16(&S->Ah[buf][ra][kc + 8], Ahg + ab + 8, avalid);
        size_t bb = (size_t)(k0 + rb) * Nc + col0 + cb;
        cp16(&S->Bh[buf][rb][cb],     Bhg + bb,     true);
        cp16(&S->Bh[buf][rb][cb + 8], Bhg + bb + 8, true);
        CP_COMMIT;
    };

    issue(0, 0);
    issue(1, 1);
    int buf = 0, nbuf = 2;
    #pragma unroll 1
    for (int c = 0; c < nch; c++) {
        CP_WAIT1;
        __syncthreads();
        if (c + 2 < nch) issue(c + 2, nbuf);
        #pragma unroll
        for (int ks = 0; ks < 2; ks++) {
            unsigned a[2][4];
            #pragma unroll
            for (int mt = 0; mt < 2; mt++) {
                unsigned ad = sptr(&S->Ah[buf][wm*32 + mt*16 + lr][ks*16 + lc]);
                LDMX4(a[mt], ad);
            }
            unsigned bf[4][4];
            #pragma unroll
            for (int g = 0; g < 4; g++) {
                unsigned bd = sptr(&S->Bh[buf][ks*16 + lr][wn*64 + g*16 + lc]);
                LDMX4T(bf[g], bd);
            }
            #pragma unroll
            for (int mt = 0; mt < 2; mt++)
                #pragma unroll
                for (int g = 0; g < 4; g++) {
                    mma16816(acc[mt][2*g],     a[mt], &bf[g][0]);
                    mma16816(acc[mt][2*g + 1], a[mt], &bf[g][2]);
                }
        }
        buf = (buf == 2) ? 0 : buf + 1;
        nbuf = (nbuf == 2) ? 0 : nbuf + 1;
    }
}

// ---------------- generic GEMM: fp32 out (bias/resid) OR fp16 out ----------------
__global__ void __launch_bounds__(256) gemm128(
        const __half* __restrict__ Ahg,
        int woff, const float* __restrict__ bias, const float* __restrict__ resid,
        float* __restrict__ out, __half* __restrict__ oh,
        int Mr, int Nc, int Kd) {
    extern __shared__ char smraw[];
    SmemGemm* S = (SmemGemm*)smraw;
    int tid = threadIdx.x;
    int row0 = blockIdx.y * 128, col0 = blockIdx.x * 128;
    float acc[2][8][4] = {};
    mma_core(Ahg, g_w + woff, nullptr, Mr, Nc, Kd, row0, col0, S, acc);
    int w = tid >> 5, lane = tid & 31;
    int wm = w & 3, wn = w >> 2;
    int r0 = lane >> 2, tq = lane & 3;
    #pragma unroll
    for (int mt = 0; mt < 2; mt++) {
        #pragma unroll
        for (int nt = 0; nt < 8; nt++) {
            int col = col0 + wn*64 + nt*8 + tq*2;
            float2 bs = *(const float2*)(bias + col);
            #pragma unroll
            for (int half = 0; half < 2; half++) {
                int row = row0 + wm*32 + mt*16 + r0 + half*8;
                if (row >= Mr) continue;
                float v0 = acc[mt][nt][half*2]     + bs.x;
                float v1 = acc[mt][nt][half*2 + 1] + bs.y;
                if (resid) {
                    float2 rr = *(const float2*)(resid + (size_t)row * Nc + col);
                    v0 += rr.x; v1 += rr.y;
                }
                if (out) {
                    float2 st = make_float2(v0, v1);
                    *(float2*)(out + (size_t)row * Nc + col) = st;
                } else {
                    *(unsigned*)(oh + (size_t)row * Nc + col) = pk2h(v0, v1);
                }
            }
        }
    }
}

// ---------------- fused K+V projection -> fp16 ----------------
__global__ void __launch_bounds__(256) kvgemm128(
        const __half* __restrict__ Ahg,
        int woffk, const float* __restrict__ bk,
        int woffv, const float* __restrict__ bv,
        __half* __restrict__ okh, __half* __restrict__ ovh,
        int Mr, int Kd) {
    extern __shared__ char smraw[];
    SmemGemm* S = (SmemGemm*)smraw;
    int woff          = (blockIdx.x == 0) ? woffk : woffv;
    const float* bias = (blockIdx.x == 0) ? bk : bv;
    __half* oh        = (blockIdx.x == 0) ? okh : ovh;
    int tid = threadIdx.x;
    int row0 = blockIdx.y * 128;
    float acc[2][8][4] = {};
    mma_core(Ahg, g_w + woff, nullptr, Mr, KVDIM, Kd, row0, 0, S, acc);
    int w = tid >> 5, lane = tid & 31;
    int wm = w & 3, wn = w >> 2;
    int r0 = lane >> 2, tq = lane & 3;
    #pragma unroll
    for (int mt = 0; mt < 2; mt++) {
        #pragma unroll
        for (int nt = 0; nt < 8; nt++) {
            int col = wn*64 + nt*8 + tq*2;
            float2 bs = *(const float2*)(bias + col);
            #pragma unroll
            for (int half = 0; half < 2; half++) {
                int row = row0 + wm*32 + mt*16 + r0 + half*8;
                if (row >= Mr) continue;
                float v0 = acc[mt][nt][half*2]     + bs.x;
                float v1 = acc[mt][nt][half*2 + 1] + bs.y;
                *(unsigned*)(oh + (size_t)row * KVDIM + col) = pk2h(v0, v1);
            }
        }
    }
}

// ---------------- FA2 flash attention: mma.m16n8k16 fp16 ----------------
#define KPAD 72
__global__ void __launch_bounds__(256) flash_mma(
        const __half* __restrict__ qh, const __half* __restrict__ kh,
        const __half* __restrict__ vh, __half* __restrict__ oh,
        int n_kv, int causal) {
    __shared__ __half Kh[64][KPAD], Vth[64][KPAD];
    int qt = blockIdx.x, h = blockIdx.y, b = blockIdx.z;
    int g = h >> 2;
    int tid = threadIdx.x, w = tid >> 5, lane = tid & 31;
    int r0 = lane >> 2, tq = lane & 3;
    int qrow = qt * 128 + w * 16 + r0;

    unsigned qah[4][4];
    {
        const __half* q0 = qh + ((size_t)(b * NN + qrow)) * CC + h * DD;
        const __half* q1 = qh + ((size_t)(b * NN + qrow + 8)) * CC + h * DD;
        #pragma unroll
        for (int ks = 0; ks < 4; ks++) {
            int c = ks * 16 + tq * 2;
            qah[ks][0] = *(const unsigned*)(q0 + c);
            qah[ks][1] = *(const unsigned*)(q1 + c);
            qah[ks][2] = *(const unsigned*)(q0 + c + 8);
            qah[ks][3] = *(const unsigned*)(q1 + c + 8);
        }
    }

    float m0 = -1e30f, m1 = -1e30f, l0 = 0.0f, l1 = 0.0f;
    float o[8][4] = {};

    int key_l = tid >> 2, dseg = (tid & 3) * 16;
    int nkt = causal ? (2 * qt + 2) : (n_kv / 64);
    for (int kt = 0; kt < nkt; kt++) {
        __syncthreads();
        {
            size_t base = ((size_t)(b * n_kv + kt * 64 + key_l)) * KVDIM + g * DD + dseg;
            *(uint4*)&Kh[key_l][dseg]     = *(const uint4*)(kh + base);
            *(uint4*)&Kh[key_l][dseg + 8] = *(const uint4*)(kh + base + 8);
            const __half* vp = vh + base;
            #pragma unroll
            for (int i = 0; i < 16; i++)
                Vth[dseg + i][key_l] = vp[i];
        }
        __syncthreads();

        float sc[8][4] = {};
        #pragma unroll
        for (int nt = 0; nt < 8; nt++) {
            int krow = nt * 8 + r0;
            #pragma unroll
            for (int ks = 0; ks < 4; ks++) {
                int c = ks * 16 + tq * 2;
                unsigned bh[2];
                bh[0] = *(const unsigned*)&Kh[krow][c];
                bh[1] = *(const unsigned*)&Kh[krow][c + 8];
                mma16816(sc[nt], qah[ks], bh);
            }
        }
        bool maskit = causal && (kt >= 2 * qt);
        #pragma unroll
        for (int nt = 0; nt < 8; nt++) {
            #pragma unroll
            for (int j = 0; j < 4; j++) {
                float v = sc[nt][j] * 0.125f;
                if (maskit) {
                    int col = kt * 64 + nt * 8 + tq * 2 + (j & 1);
                    int row = qt * 128 + w * 16 + r0 + ((j >> 1) ? 8 : 0);
                    if (col > row) v = -1e9f;
                }
                sc[nt][j] = v;
            }
        }
        float rm0 = -1e30f, rm1 = -1e30f;
        #pragma unroll
        for (int nt = 0; nt < 8; nt++) {
            rm0 = fmaxf(rm0, fmaxf(sc[nt][0], sc[nt][1]));
            rm1 = fmaxf(rm1, fmaxf(sc[nt][2], sc[nt][3]));
        }
        #pragma unroll
        for (int off = 1; off < 4; off <<= 1) {
            rm0 = fmaxf(rm0, __shfl_xor_sync(0xffffffffu, rm0, off));
            rm1 = fmaxf(rm1, __shfl_xor_sync(0xffffffffu, rm1, off));
        }
        float mn0 = fmaxf(m0, rm0), mn1 = fmaxf(m1, rm1);
        float al0 = __expf(m0 - mn0), al1 = __expf(m1 - mn1);
        m0 = mn0; m1 = mn1;
        float rs0 = 0.0f, rs1 = 0.0f;
        #pragma unroll
        for (int nt = 0; nt < 8; nt++) {
            sc[nt][0] = __expf(sc[nt][0] - mn0);
            sc[nt][1] = __expf(sc[nt][1] - mn0);
            sc[nt][2] = __expf(sc[nt][2] - mn1);
            sc[nt][3] = __expf(sc[nt][3] - mn1);
            rs0 += sc[nt][0] + sc[nt][1];
            rs1 += sc[nt][2] + sc[nt][3];
        }
        #pragma unroll
        for (int off = 1; off < 4; off <<= 1) {
            rs0 += __shfl_xor_sync(0xffffffffu, rs0, off);
            rs1 += __shfl_xor_sync(0xffffffffu, rs1, off);
        }
        l0 = l0 * al0 + rs0;
        l1 = l1 * al1 + rs1;
        #pragma unroll
        for (int nt = 0; nt < 8; nt++) {
            o[nt][0] *= al0; o[nt][1] *= al0;
            o[nt][2] *= al1; o[nt][3] *= al1;
        }
        #pragma unroll
        for (int kp = 0; kp < 4; kp++) {
            unsigned pah[4];
            pah[0] = pk2h(sc[2*kp][0],   sc[2*kp][1]);
            pah[1] = pk2h(sc[2*kp][2],   sc[2*kp][3]);
            pah[2] = pk2h(sc[2*kp+1][0], sc[2*kp+1][1]);
            pah[3] = pk2h(sc[2*kp+1][2], sc[2*kp+1][3]);
            #pragma unroll
            for (int nt = 0; nt < 8; nt++) {
                int drow = nt * 8 + r0;
                int c = kp * 16 + tq * 2;
                unsigned bh[2];
                bh[0] = *(const unsigned*)&Vth[drow][c];
                bh[1] = *(const unsigned*)&Vth[drow][c + 8];
                mma16816(o[nt], pah, bh);
            }
        }
    }
    float inv0 = 1.0f / l0, inv1 = 1.0f / l1;
    size_t base0 = ((size_t)(b * NN + qrow)) * CC + h * DD;
    size_t base1 = ((size_t)(b * NN + qrow + 8)) * CC + h * DD;
    #pragma unroll
    for (int nt = 0; nt < 8; nt++) {
        int d = nt * 8 + tq * 2;
        *(unsigned*)(oh + base0 + d) = pk2h(o[nt][0] * inv0, o[nt][1] * inv0);
        *(unsigned*)(oh + base1 + d) = pk2h(o[nt][2] * inv1, o[nt][3] * inv1);
    }
}

// ---------------- MoE routing ----------------
__global__ void zero_kernel() {
    int t = threadIdx.x;
    if (t < EE) { g_count[t] = 0; g_Psum[t] = 0.0f; }
}

__global__ void router_kernel(const float* __restrict__ rw, const float* __restrict__ rb) {
    __shared__ float sP[EE];
    int tid = threadIdx.x;
    if (tid < EE) sP[tid] = 0.0f;
    __syncthreads();
    int t = blockIdx.x * blockDim.x + tid;
    float logit[EE];
    const float* hrow = g_h + (size_t)t * CC;
    #pragma unroll
    for (int e = 0; e < EE; e++) logit[e] = rb[e];
    for (int k = 0; k < CC; k++) {
        float hv = hrow[k];
        const float* wr = rw + k * EE;
        #pragma unroll
        for (int e = 0; e < EE; e++) logit[e] += hv * wr[e];
    }
    float mx = logit[0];
    #pragma unroll
    for (int e = 1; e < EE; e++) mx = fmaxf(mx, logit[e]);
    float p[EE], ps = 0.0f;
    #pragma unroll
    for (int e = 0; e < EE; e++) { p[e] = __expf(logit[e] - mx); ps += p[e]; }
    float invs = 1.0f / ps;
    #pragma unroll
    for (int e = 0; e < EE; e++) p[e] *= invs;
    int i0 = 0;
    #pragma unroll
    for (int e = 1; e < EE; e++) if (p[e] > p[i0]) i0 = e;
    int i1 = (i0 == 0) ? 1 : 0;
    #pragma unroll
    for (int e = 0; e < EE; e++) if (e != i0 && p[e] > p[i1]) i1 = e;
    float gs = p[i0] + p[i1];
    float g0 = p[i0] / gs, g1 = p[i1] / gs;
    int s0 = atomicAdd(&g_count[i0], 1);
    int s1 = atomicAdd(&g_count[i1], 1);
    int r0 = i0 * EROWS + s0, r1 = i1 * EROWS + s1;
    g_tok_of_row[r0] = t; g_tok_of_row[r1] = t;
    g_tokrow[t * 2] = r0; g_tokrow[t * 2 + 1] = r1;
    g_tokgate[t * 2] = g0; g_tokgate[t * 2 + 1] = g1;
    #pragma unroll
    for (int e = 0; e < EE; e++) atomicAdd(&sP[e], p[e]);
    __syncthreads();
    if (tid < EE) atomicAdd(&g_Psum[tid], sP[tid]);
}

// ---------------- expert GEMM 1 (gathered A, GELU -> mid fp16) ----------------
__global__ void __launch_bounds__(256) egemm1_kernel(const float* __restrict__ eb1) {
    int e = blockIdx.z;
    int cnt = g_count[e];
    int row0 = blockIdx.y * 128;
    if (row0 >= cnt) return;
    int col0 = blockIdx.x * 128;
    extern __shared__ char smraw[];
    SmemGemm* S = (SmemGemm*)smraw;
    __shared__ int s_tok[128];
    int tid = threadIdx.x;
    if (tid < 128) {
        int gr = row0 + tid;
        s_tok[tid] = (gr < cnt) ? g_tok_of_row[e * EROWS + gr] : -1;
    }
    __syncthreads();
    float acc[2][8][4] = {};
    size_t woff = OFF_EW1 + (size_t)e * CC * FF;
    mma_core(g_hx, g_w + woff, s_tok, 0, FF, CC, 0, col0, S, acc);
    int w = tid >> 5, lane = tid & 31;
    int wm = w & 3, wn = w >> 2;
    int r0 = lane >> 2, tq = lane & 3;
    const float* bias = eb1 + e * FF;
    #pragma unroll
    for (int mt = 0; mt < 2; mt++) {
        #pragma unroll
        for (int nt = 0; nt < 8; nt++) {
            int col = col0 + wn*64 + nt*8 + tq*2;
            float2 bs = *(const float2*)(bias + col);
            #pragma unroll
            for (int half = 0; half < 2; half++) {
                int row = row0 + wm*32 + mt*16 + r0 + half*8;
                if (row >= cnt) continue;
                float x0 = acc[mt][nt][half*2]     + bs.x;
                float x1 = acc[mt][nt][half*2 + 1] + bs.y;
                float u0 = 0.7978845608028654f * (x0 + 0.044715f * x0 * x0 * x0);
                float u1 = 0.7978845608028654f * (x1 + 0.044715f * x1 * x1 * x1);
                float ge0 = 0.5f * x0 * (1.0f + tanhf(u0));
                float ge1 = 0.5f * x1 * (1.0f + tanhf(u1));
                *(unsigned*)(g_mid + ((size_t)e * EROWS + row) * FF + col) = pk2h(ge0, ge1);
            }
        }
    }
}

// ---------------- expert GEMM 2 ----------------
__global__ void __launch_bounds__(256) egemm2_kernel(const float* __restrict__ eb2) {
    int e = blockIdx.z;
    int cnt = g_count[e];
    int row0 = blockIdx.y * 128;
    if (row0 >= cnt) return;
    int col0 = blockIdx.x * 128;
    extern __shared__ char smraw[];
    SmemGemm* S = (SmemGemm*)smraw;
    int tid = threadIdx.x;
    float acc[2][8][4] = {};
    size_t woff = OFF_EW2 + (size_t)e * FF * CC;
    mma_core(g_mid + (size_t)e * EROWS * FF, g_w + woff, nullptr, cnt, CC, FF, row0, col0, S, acc);
    int w = tid >> 5, lane = tid & 31;
    int wm = w & 3, wn = w >> 2;
    int r0 = lane >> 2, tq = lane & 3;
    const float* bias = eb2 + e * CC;
    #pragma unroll
    for (int mt = 0; mt < 2; mt++) {
        #pragma unroll
        for (int nt = 0; nt < 8; nt++) {
            int col = col0 + wn*64 + nt*8 + tq*2;
            float2 bs = *(const float2*)(bias + col);
            #pragma unroll
            for (int half = 0; half < 2; half++) {
                int row = row0 + wm*32 + mt*16 + r0 + half*8;
                if (row >= cnt) continue;
                float2 st = make_float2(acc[mt][nt][half*2] + bs.x,
                                        acc[mt][nt][half*2 + 1] + bs.y);
                *(float2*)(g_eo + ((size_t)e * EROWS + row) * CC + col) = st;
            }
        }
    }
}

// ---------------- combine + aux ----------------
__global__ void combine_kernel(float* __restrict__ out) {
    int t = blockIdx.x;
    int tid = threadIdx.x;
    int r0 = g_tokrow[t * 2], r1 = g_tokrow[t * 2 + 1];
    float g0 = g_tokgate[t * 2], g1 = g_tokgate[t * 2 + 1];
    const float* x2 = g_x2 + (size_t)t * CC;
    const float* e0 = g_eo + (size_t)r0 * CC;
    const float* e1 = g_eo + (size_t)r1 * CC;
    float* orow = out + (size_t)t * CC;
    for (int c = tid; c < CC; c += 128)
        orow[c] = x2[c] + g0 * e0[c] + g1 * e1[c];
}

__global__ void aux_kernel(float* __restrict__ out, int out_size) {
    if (threadIdx.x == 0 && blockIdx.x == 0) {
        float a = 0.0f;
        for (int e = 0; e < EE; e++)
            a += (g_count[e] / (float)TOK) * (g_Psum[e] / (float)TOK);
        a *= (float)EE;
        if (out_size > TOK * CC) out[TOK * CC] = a;
    }
}

// ---------------- launch ----------------
extern "C" void kernel_launch(void* const* d_in, const int* in_sizes, int n_in,
                              void* d_out, int out_size) {
    const float* x      = (const float*)d_in[0];
    const float* vision = (const float*)d_in[1];
    const float* ln1_g = (const float*)d_in[2];  const float* ln1_b = (const float*)d_in[3];
    const float* ln2_g = (const float*)d_in[4];  const float* ln2_b = (const float*)d_in[5];
    const float* ln3_g = (const float*)d_in[6];  const float* ln3_b = (const float*)d_in[7];
    const float* sa_wq = (const float*)d_in[8];  const float* sa_bq = (const float*)d_in[9];
    const float* sa_wk = (const float*)d_in[10]; const float* sa_bk = (const float*)d_in[11];
    const float* sa_wv = (const float*)d_in[12]; const float* sa_bv = (const float*)d_in[13];
    const float* sa_wo = (const float*)d_in[14]; const float* sa_bo = (const float*)d_in[15];
    const float* ca_wq = (const float*)d_in[16]; const float* ca_bq = (const float*)d_in[17];
    const float* ca_wk = (const float*)d_in[18]; const float* ca_bk = (const float*)d_in[19];
    const float* ca_wv = (const float*)d_in[20]; const float* ca_bv = (const float*)d_in[21];
    const float* ca_wo = (const float*)d_in[22]; const float* ca_bo = (const float*)d_in[23];
    const float* rw    = (const float*)d_in[24]; const float* rb    = (const float*)d_in[25];
    const float* ew1   = (const float*)d_in[26]; const float* eb1   = (const float*)d_in[27];
    const float* ew2   = (const float*)d_in[28]; const float* eb2   = (const float*)d_in[29];
    float* out = (float*)d_out;

    float *p_h, *p_x1, *p_x2;
    __half *p_hx, *p_qx, *p_kx, *p_vx, *p_k2x, *p_v2x, *p_atx, *p_vix, *p_w;
    cudaGetSymbolAddress((void**)&p_h,  g_h);
    cudaGetSymbolAddress((void**)&p_x1, g_x1);
    cudaGetSymbolAddress((void**)&p_x2, g_x2);
    cudaGetSymbolAddress((void**)&p_hx, g_hx);
    cudaGetSymbolAddress((void**)&p_qx, g_qx);
    cudaGetSymbolAddress((void**)&p_kx, g_kx);
    cudaGetSymbolAddress((void**)&p_vx, g_vx);
    cudaGetSymbolAddress((void**)&p_k2x, g_k2x);
    cudaGetSymbolAddress((void**)&p_v2x, g_v2x);
    cudaGetSymbolAddress((void**)&p_atx, g_atx);
    cudaGetSymbolAddress((void**)&p_vix, g_vix);
    cudaGetSymbolAddress((void**)&p_w,  g_w);

    const int gemm_smem = GEMM_SMEM_BYTES;
    cudaFuncSetAttribute(gemm128,       cudaFuncAttributeMaxDynamicSharedMemorySize, gemm_smem);
    cudaFuncSetAttribute(kvgemm128,     cudaFuncAttributeMaxDynamicSharedMemorySize, gemm_smem);
    cudaFuncSetAttribute(egemm1_kernel, cudaFuncAttributeMaxDynamicSharedMemorySize, gemm_smem);
    cudaFuncSetAttribute(egemm2_kernel, cudaFuncAttributeMaxDynamicSharedMemorySize, gemm_smem);

    static cudaStream_t s1 = nullptr, s2 = nullptr;
    static cudaEvent_t evF = nullptr, evB = nullptr, evKV = nullptr, evLn1 = nullptr;
    if (!s1) {
        cudaStreamCreateWithFlags(&s1, cudaStreamNonBlocking);
        cudaStreamCreateWithFlags(&s2, cudaStreamNonBlocking);
        cudaEventCreateWithFlags(&evF,   cudaEventDisableTiming);
        cudaEventCreateWithFlags(&evB,   cudaEventDisableTiming);
        cudaEventCreateWithFlags(&evKV,  cudaEventDisableTiming);
        cudaEventCreateWithFlags(&evLn1, cudaEventDisableTiming);
    }

    dim3 gC(CC / 128, TOK / 128);
    dim3 gKVsa(2, TOK / 128);
    dim3 gKVca(2, (BB * MV) / 128);
    dim3 gAtt(NN / 128, HH, BB);

    auto conv = [&](const float* src, size_t off, int n, cudaStream_t st) {
        conv_kernel<<<(n / 4 + 255) / 256, 256, 0, st>>>(src, p_w + off, n);
    };

    // ---- fork s1: everything independent of block 1 ----
    cudaEventRecord(evF, 0);
    cudaStreamWaitEvent(s1, evF, 0);
    conv(ca_wq, OFF_CAWQ, SZ_QO, s1); conv(ca_wk, OFF_CAWK, SZ_KV, s1);
    conv(ca_wv, OFF_CAWV, SZ_KV, s1); conv(ca_wo, OFF_CAWO, SZ_QO, s1);
    conv_kernel<<<(BB * MV * CC / 4 + 255) / 256, 256, 0, s1>>>(vision, p_vix, BB * MV * CC);
    conv(ew1, OFF_EW1, EE * CC * FF, s1);
    conv(ew2, OFF_EW2, EE * FF * CC, s1);
    kvgemm128<<<gKVca, 256, gemm_smem, s1>>>(p_vix, OFF_CAWK, ca_bk, OFF_CAWV, ca_bv,
                                             p_k2x, p_v2x, BB * MV, CC);
    cudaEventRecord(evB, s1);

    // ---- main stream: SA weight conv + block 1 ----
    conv(sa_wq, OFF_SAWQ, SZ_QO, 0); conv(sa_wk, OFF_SAWK, SZ_KV, 0);
    conv(sa_wv, OFF_SAWV, SZ_KV, 0); conv(sa_wo, OFF_SAWO, SZ_QO, 0);
    ln_kernel<<<TOK, 256>>>(x, ln1_g, ln1_b, nullptr, p_hx);
    cudaEventRecord(evLn1, 0);
    cudaStreamWaitEvent(s2, evLn1, 0);
    kvgemm128<<<gKVsa, 256, gemm_smem, s2>>>(p_hx, OFF_SAWK, sa_bk, OFF_SAWV, sa_bv,
                                             p_kx, p_vx, TOK, CC);
    cudaEventRecord(evKV, s2);
    gemm128<<<gC, 256, gemm_smem>>>(p_hx, OFF_SAWQ, sa_bq, nullptr,
                                    nullptr, p_qx, TOK, CC, CC);
    cudaStreamWaitEvent(0, evKV, 0);
    flash_mma<<<gAtt, 256>>>(p_qx, p_kx, p_vx, p_atx, NN, 1);
    gemm128<<<gC, 256, gemm_smem>>>(p_atx, OFF_SAWO, sa_bo, x,
                                    p_x1, nullptr, TOK, CC, CC);

    // ---- block 2: CA ----
    ln_kernel<<<TOK, 256>>>(p_x1, ln2_g, ln2_b, nullptr, p_hx);
    cudaStreamWaitEvent(0, evB, 0);
    gemm128<<<gC, 256, gemm_smem>>>(p_hx, OFF_CAWQ, ca_bq, nullptr,
                                    nullptr, p_qx, TOK, CC, CC);
    flash_mma<<<gAtt, 256>>>(p_qx, p_k2x, p_v2x, p_atx, MV, 0);
    gemm128<<<gC, 256, gemm_smem>>>(p_atx, OFF_CAWO, ca_bo, p_x1,
                                    p_x2, nullptr, TOK, CC, CC);

    // ---- block 3: MoE ----
    ln_kernel<<<TOK, 256>>>(p_x2, ln3_g, ln3_b, p_h, p_hx);
    zero_kernel<<<1, 32>>>();
    router_kernel<<<TOK / 256, 256>>>(rw, rb);
    egemm1_kernel<<<dim3(FF / 128, EROWS / 128, EE), 256, gemm_smem>>>(eb1);
    egemm2_kernel<<<dim3(CC / 128, EROWS / 128, EE), 256, gemm_smem>>>(eb2);
    combine_kernel<<<TOK, 128>>>(out);
    aux_kernel<<<1, 1>>>(out, out_size);
}